// round 9
// baseline (speedup 1.0000x reference)
#include <cuda_runtime.h>
#include <math.h>
#include <stdint.h>

// Problem constants
#define BB   128
#define TT   1024
#define VV   256
#define EE   128
#define HH   1024
#define DD   512
#define SS   5
#define G4H  4096
#define NCTA 128

// h-state in A-fragment layout: [t][kb 0..127][mt 0..7][lane 0..31][slot 0..3] floats
#define HF_T 131072

// rnn smem layout (byte offsets from 1024-aligned base)
#define SM_B   0               // B fragments: 128KB
#define SM_A   131072          // A stages: 2 x 32KB
#define SM_CS  196608          // C tile [128][36] floats
#define SM_CTL 215040          // full0 +0, full1 +8, free0 +16, free1 +24
#define SM_TOTAL (215040 + 64)

// logits smem layout
#define LG_A   0               // A stages: 2 x 32KB
#define LG_B   65536           // B stages: 2 x 64KB
#define LG_CTL 196608
#define LG_TOTAL (196608 + 64)

// ---------------- device scratch -------------------------------------------------------
__device__ float g_a2tab[VV * SS];
__device__ float g_gx_tab[VV * G4H];
__device__ float g_attn_tab[VV * G4H];
__device__ float g_Wcomb[VV * HH];
__device__ float g_bcomb[VV];
__device__ float g_h0f[HF_T];
__device__ float g_hsf[(size_t)TT * HF_T];
__device__ float2 g_WcombF[128 * 32 * 32];          // Wcomb B-fragments (1 MB)
__device__ int   g_ready[TT * 16];                  // per (t, chunk) producer counters

__device__ __forceinline__ float sigm(float x) { return 1.0f / (1.0f + __expf(-x)); }
__device__ __forceinline__ uint32_t f2tf32(float f) {
    uint32_t u;
    asm("cvt.rna.tf32.f32 %0, %1;" : "=r"(u) : "f"(f));
    return u;
}
__device__ __forceinline__ uint32_t smem_u32(const void* p) {
    uint32_t a;
    asm("{ .reg .u64 t; cvta.to.shared.u64 t, %1; cvt.u32.u64 %0, t; }" : "=r"(a) : "l"(p));
    return a;
}

#define MBAR_INIT(a, n) asm volatile("mbarrier.init.shared.b64 [%0], %1;" :: "r"(a), "r"((uint32_t)(n)) : "memory")
#define MBAR_ARRIVE(a)  asm volatile("mbarrier.arrive.shared.b64 _, [%0];" :: "r"(a) : "memory")
#define MBAR_EXPECT_TX(a, b) asm volatile("mbarrier.arrive.expect_tx.shared.b64 _, [%0], %1;" :: "r"(a), "r"((uint32_t)(b)) : "memory")
#define MBAR_WAIT(a, par) do { \
    uint32_t _m = (a), _p = (par), _d; \
    asm volatile("{ .reg .pred p; mbarrier.try_wait.parity.acquire.cta.shared::cta.b64 p, [%1], %2; selp.b32 %0,1,0,p; }" \
                 : "=r"(_d) : "r"(_m), "r"(_p) : "memory"); \
    if (!_d) { \
        asm volatile("{ .reg .pred P1; WL_%=: mbarrier.try_wait.parity.acquire.cta.shared::cta.b64 P1, [%0], %1, 0x989680; " \
                     "@P1 bra.uni WD_%=; bra.uni WL_%=; WD_%=: }" :: "r"(_m), "r"(_p) : "memory"); \
    } } while (0)

#define BULK_CP(dst, src, bytes, mbar) \
    asm volatile("cp.async.bulk.shared::cluster.global.mbarrier::complete_tx::bytes [%0], [%1], %2, [%3];" \
                 :: "r"(dst), "l"(src), "r"((uint32_t)(bytes)), "r"(mbar) : "memory")

#define LDS128(r, addr) \
    asm volatile("ld.shared.v4.b32 {%0,%1,%2,%3}, [%4];" \
                 : "=r"((r)[0]), "=r"((r)[1]), "=r"((r)[2]), "=r"((r)[3]) : "r"(addr))
#define LDS64(r0, r1, addr) \
    asm volatile("ld.shared.v2.b32 {%0,%1}, [%2];" : "=r"(r0), "=r"(r1) : "r"(addr))

#define MMA_TF32(acc, a, b0, b1) \
    asm volatile("mma.sync.aligned.m16n8k8.row.col.f32.tf32.tf32.f32 " \
                 "{%0,%1,%2,%3}, {%4,%5,%6,%7}, {%8,%9}, {%0,%1,%2,%3};" \
                 : "+f"((acc)[0]), "+f"((acc)[1]), "+f"((acc)[2]), "+f"((acc)[3]) \
                 : "r"((a)[0]), "r"((a)[1]), "r"((a)[2]), "r"((a)[3]), "r"(b0), "r"(b1))

// ---------------- prep kernels ---------------------------------------------------------
__global__ void senti_tab_kernel(const float* __restrict__ emb,
                                 const float* __restrict__ s1_Wih, const float* __restrict__ s1_bih,
                                 const float* __restrict__ s1_bhh, const float* __restrict__ s1_Wd,
                                 const float* __restrict__ s1_bd,
                                 const float* __restrict__ s2_Wih, const float* __restrict__ s2_bih,
                                 const float* __restrict__ s2_bhh, const float* __restrict__ s2_Wd,
                                 const float* __restrict__ s2_bd) {
    int v = blockIdx.x * blockDim.x + threadIdx.x;
    if (v >= VV) return;
    float h1[8];
    {
        float g[32];
        const float* e = emb + v * EE;
        for (int j = 0; j < 32; j++) {
            const float* w = s1_Wih + j * EE;
            float a = s1_bih[j] + s1_bhh[j];
            for (int k = 0; k < EE; k++) a += e[k] * w[k];
            g[j] = a;
        }
        for (int u = 0; u < 8; u++) {
            float cc = sigm(g[u]) * tanhf(g[16 + u]);
            h1[u] = sigm(g[24 + u]) * tanhf(cc);
        }
    }
    float a1[SS];
    {
        float l[SS], m = -1e30f;
        for (int s = 0; s < SS; s++) {
            float a = s1_bd[s];
            for (int u = 0; u < 8; u++) a += h1[u] * s1_Wd[s * 8 + u];
            l[s] = a; m = fmaxf(m, a);
        }
        float sum = 0.0f;
        for (int s = 0; s < SS; s++) { l[s] = __expf(l[s] - m); sum += l[s]; }
        for (int s = 0; s < SS; s++) a1[s] = l[s] / sum;
    }
    float h2[8];
    {
        float g[32];
        for (int j = 0; j < 32; j++) {
            const float* w = s2_Wih + j * SS;
            float a = s2_bih[j] + s2_bhh[j];
            for (int s = 0; s < SS; s++) a += a1[s] * w[s];
            g[j] = a;
        }
        for (int u = 0; u < 8; u++) {
            float cc = sigm(g[u]) * tanhf(g[16 + u]);
            h2[u] = sigm(g[24 + u]) * tanhf(cc);
        }
    }
    {
        float l[SS], m = -1e30f;
        for (int s = 0; s < SS; s++) {
            float a = s2_bd[s];
            for (int u = 0; u < 8; u++) a += h2[u] * s2_Wd[s * 8 + u];
            l[s] = a; m = fmaxf(m, a);
        }
        float sum = 0.0f;
        for (int s = 0; s < SS; s++) { l[s] = __expf(l[s] - m); sum += l[s]; }
        for (int s = 0; s < SS; s++) g_a2tab[v * SS + s] = l[s] / sum;
    }
}

__global__ __launch_bounds__(256) void tab_kernel(const float* __restrict__ emb,
                                                  const float* __restrict__ Wih,
                                                  const float* __restrict__ bih,
                                                  const float* __restrict__ bhh) {
    int v = blockIdx.x;
    __shared__ float se[EE];
    __shared__ float sa[SS];
    if (threadIdx.x < EE) se[threadIdx.x] = emb[v * EE + threadIdx.x];
    if (threadIdx.x < SS) sa[threadIdx.x] = g_a2tab[v * SS + threadIdx.x];
    __syncthreads();
    for (int j = threadIdx.x; j < G4H; j += 256) {
        const float* w = Wih + (size_t)j * (EE + SS);
        float a = bih[j] + bhh[j];
        for (int k = 0; k < EE; k++) a += se[k] * w[k];
        g_gx_tab[v * G4H + j] = a;
        float at = 0.0f;
        for (int s = 0; s < SS; s++) at += sa[s] * w[EE + s];
        g_attn_tab[v * G4H + j] = at;
    }
}

__global__ __launch_bounds__(256) void wcomb_kernel(const float* __restrict__ Wd,
                                                    const float* __restrict__ bd,
                                                    const float* __restrict__ Wo,
                                                    const float* __restrict__ bo) {
    int o = blockIdx.x;
    __shared__ float swo[DD];
    for (int i = threadIdx.x; i < DD; i += 256) swo[i] = Wo[o * DD + i];
    __syncthreads();
    for (int k = threadIdx.x; k < HH; k += 256) {
        float a = 0.0f;
        for (int d = 0; d < DD; d++) a += swo[d] * Wd[d * HH + k];
        g_Wcomb[o * HH + k] = a;
    }
    if (threadIdx.x == 0) {
        float a = bo[o];
        for (int d = 0; d < DD; d++) a += swo[d] * bd[d];
        g_bcomb[o] = a;
    }
}

// pack Wcomb into B-fragment layout (tf32-rounded): [kb][nblk][lane] float2
__global__ __launch_bounds__(256) void wpack_kernel() {
    int kb = blockIdx.x;
    for (int i = threadIdx.x; i < 1024; i += 256) {
        int nb = i >> 5, L = i & 31;
        int o = nb * 8 + (L >> 2);
        int k = kb * 8 + (L & 3);
        float2 v;
        v.x = __uint_as_float(f2tf32(g_Wcomb[(size_t)o * HH + k]));
        v.y = __uint_as_float(f2tf32(g_Wcomb[(size_t)o * HH + k + 4]));
        g_WcombF[(kb * 32 + nb) * 32 + L] = v;
    }
}

__global__ void init_kernel() {
    int idx = blockIdx.x * blockDim.x + threadIdx.x;
    if (idx < HF_T) g_h0f[idx] = 0.0f;
    if (idx < TT * 16) g_ready[idx] = 0;
}

// ---------------- persistent recurrence: dataflow-synced, warp-specialized -------------
// 128 CTAs x 288 thr. Warps 0-3: MMA consumers (m32 each). Warps 4-7: pointwise
// (thread b = tid-128, cell state in regs). Warp 8 lane 0: bulk-copy producer,
// gated per-chunk by g_ready counters (set by the 8 CTAs owning that chunk's slabs).
__global__ __launch_bounds__(288, 1) void rnn5_kernel(const int* __restrict__ x,
                                                      const float* __restrict__ Whh) {
    extern __shared__ char smraw[];
    uint32_t sb0 = smem_u32(smraw);
    uint32_t sb = (sb0 + 1023u) & ~1023u;
    char* smem = smraw + (sb - sb0);
    float* Cs = (float*)(smem + SM_CS);

    const int tid = threadIdx.x;
    const int jt  = blockIdx.x;
    const int w   = tid >> 5;
    const int l   = tid & 31;

    // pack B fragments (tf32-rounded)
    {
        float4* Bp = (float4*)(smem + SM_B);
        for (int i = tid; i < 8192; i += 288) {
            int kb = i >> 6;
            int np = (i >> 5) & 1;
            int L  = i & 31;
            int tig = L & 3, g0 = L >> 2;
            int j0 = (2 * np) * 1024 + jt * 8 + g0;
            int j1 = j0 + 1024;
            int k0 = kb * 8 + tig;
            float4 v;
            v.x = __uint_as_float(f2tf32(Whh[(size_t)j0 * HH + k0]));
            v.y = __uint_as_float(f2tf32(Whh[(size_t)j0 * HH + k0 + 4]));
            v.z = __uint_as_float(f2tf32(Whh[(size_t)j1 * HH + k0]));
            v.w = __uint_as_float(f2tf32(Whh[(size_t)j1 * HH + k0 + 4]));
            Bp[i] = v;
        }
    }
    if (tid == 0) {
        MBAR_INIT(sb + SM_CTL + 0, 1);
        MBAR_INIT(sb + SM_CTL + 8, 1);
        MBAR_INIT(sb + SM_CTL + 16, 4);
        MBAR_INIT(sb + SM_CTL + 24, 4);
    }
    __syncthreads();

    float creg[8] = {0.f, 0.f, 0.f, 0.f, 0.f, 0.f, 0.f, 0.f};
    float gadd[4][8];

    for (int t = 0; t < TT; t++) {
        if (w < 4) {
            // ================= MMA consumers =================
            float acc[2][4][4];
#pragma unroll
            for (int m = 0; m < 2; m++)
#pragma unroll
                for (int n = 0; n < 4; n++)
#pragma unroll
                    for (int q = 0; q < 4; q++) acc[m][n][q] = 0.f;

            for (int s = 0; s < 16; s++) {
                unsigned u = (unsigned)(t * 8 + (s >> 1));
                MBAR_WAIT(sb + SM_CTL + (s & 1) * 8, u & 1u);
                uint32_t abase = sb + SM_A + (s & 1) * 32768;
#pragma unroll
                for (int kbi = 0; kbi < 8; kbi++) {
                    int kb = s * 8 + kbi;
                    uint32_t aaddr = abase + (uint32_t)(((kbi * 8 + 2 * w) * 32 + l) * 16);
                    uint32_t baddr = sb + SM_B + (uint32_t)(((kb * 2) * 32 + l) * 16);
                    uint32_t a0[4], a1[4], b0[4], b1[4];
                    LDS128(a0, aaddr);
                    LDS128(a1, aaddr + 512);
                    LDS128(b0, baddr);
                    LDS128(b1, baddr + 512);
                    MMA_TF32(acc[0][0], a0, b0[0], b0[1]);
                    MMA_TF32(acc[0][1], a0, b0[2], b0[3]);
                    MMA_TF32(acc[0][2], a0, b1[0], b1[1]);
                    MMA_TF32(acc[0][3], a0, b1[2], b1[3]);
                    MMA_TF32(acc[1][0], a1, b0[0], b0[1]);
                    MMA_TF32(acc[1][1], a1, b0[2], b0[3]);
                    MMA_TF32(acc[1][2], a1, b1[0], b1[1]);
                    MMA_TF32(acc[1][3], a1, b1[2], b1[3]);
                }
                if (l == 0) MBAR_ARRIVE(sb + SM_CTL + 16 + (s & 1) * 8);
            }
            int gID = l >> 2, tig = l & 3;
#pragma unroll
            for (int mtl = 0; mtl < 2; mtl++) {
                int rb = w * 32 + mtl * 16 + gID;
#pragma unroll
                for (int nb = 0; nb < 4; nb++) {
                    *(float2*)&Cs[rb * 36 + nb * 8 + 2 * tig] =
                        make_float2(acc[mtl][nb][0], acc[mtl][nb][1]);
                    *(float2*)&Cs[(rb + 8) * 36 + nb * 8 + 2 * tig] =
                        make_float2(acc[mtl][nb][2], acc[mtl][nb][3]);
                }
            }
        } else if (w == 8) {
            // ================= producer (lane 0): dataflow-gated bulk copies ========
            if (l == 0) {
                const float* src = t ? (g_hsf + (size_t)(t - 1) * HF_T) : g_h0f;
                const int* rb = g_ready + (t - 1) * 16;
                for (int s = 0; s < 16; s++) {
                    if (t > 0) {
                        int v;
                        do {
                            asm volatile("ld.global.cg.b32 %0, [%1];" : "=r"(v) : "l"(rb + s) : "memory");
                            if (v >= 8) break;
                            __nanosleep(32);
                        } while (1);
                        __threadfence();
                    }
                    unsigned u = (unsigned)(t * 8 + (s >> 1));
                    if (u > 0) MBAR_WAIT(sb + SM_CTL + 16 + (s & 1) * 8, (u - 1) & 1u);
                    MBAR_EXPECT_TX(sb + SM_CTL + (s & 1) * 8, 32768);
                    BULK_CP(sb + SM_A + (s & 1) * 32768, src + s * 8192, 32768,
                            sb + SM_CTL + (s & 1) * 8);
                }
            }
        } else {
            // ================= pointwise warps: prefetch gate-input tables =========
            int b = tid - 128;
            int tok = __ldg(&x[b * TT + t]);
            const float* gx = g_gx_tab + (size_t)tok * G4H + (jt << 3);
#pragma unroll
            for (int gate = 0; gate < 4; gate++) {
                float4 p0 = *(const float4*)(gx + (gate << 10));
                float4 p1 = *(const float4*)(gx + (gate << 10) + 4);
                gadd[gate][0] = p0.x; gadd[gate][1] = p0.y; gadd[gate][2] = p0.z; gadd[gate][3] = p0.w;
                gadd[gate][4] = p1.x; gadd[gate][5] = p1.y; gadd[gate][6] = p1.z; gadd[gate][7] = p1.w;
            }
            if (t > 0) {
                int pt = __ldg(&x[b * TT + t - 1]);
                const float* at = g_attn_tab + (size_t)pt * G4H + (jt << 3);
#pragma unroll
                for (int gate = 0; gate < 4; gate++) {
                    float4 p0 = *(const float4*)(at + (gate << 10));
                    float4 p1 = *(const float4*)(at + (gate << 10) + 4);
                    gadd[gate][0] += p0.x; gadd[gate][1] += p0.y; gadd[gate][2] += p0.z; gadd[gate][3] += p0.w;
                    gadd[gate][4] += p1.x; gadd[gate][5] += p1.y; gadd[gate][6] += p1.z; gadd[gate][7] += p1.w;
                }
            }
        }
        __syncthreads();

        // ================= pointwise: LSTM + h store + ready flag =================
        if (w >= 4 && w < 8) {
            int b = tid - 128;
            int mt = b >> 4, ri = b & 15;
            float* hdst = g_hsf + ((size_t)t * 128 + jt) * 1024 + mt * 128;
#pragma unroll
            for (int uu = 0; uu < 8; uu++) {
                float gi = Cs[b * 36 + uu]      + gadd[0][uu];
                float gf = Cs[b * 36 + 8 + uu]  + gadd[1][uu];
                float gg = Cs[b * 36 + 16 + uu] + gadd[2][uu];
                float go = Cs[b * 36 + 24 + uu] + gadd[3][uu];
                float cn = sigm(gf) * creg[uu] + sigm(gi) * tanhf(gg);
                float hn = sigm(go) * tanhf(cn);
                creg[uu] = cn;
                int L = (ri & 7) * 4 + (uu & 3);
                int slot = ((uu >= 4) ? 2 : 0) + ((ri >= 8) ? 1 : 0);
                hdst[L * 4 + slot] = __uint_as_float(f2tf32(hn));
            }
            __threadfence();
            asm volatile("bar.sync 2, 128;" ::: "memory");
            if (tid == 128) atomicAdd(&g_ready[t * 16 + (jt >> 3)], 1);
        }
        __syncthreads();
    }
}

// ---------------- epilogue: tf32 MMA logits + log_softmax ------------------------------
// 1024 CTAs (one per t) x 288 thr. Warps 0-7: m16 rows each, all 256 cols.
// Warp 8 lane 0: bulk-copy producer (A chunk 32KB + B chunk 64KB per stage).
__global__ __launch_bounds__(288, 1) void logits_kernel(float* __restrict__ out) {
    extern __shared__ char smraw[];
    uint32_t sb0 = smem_u32(smraw);
    uint32_t sb = (sb0 + 1023u) & ~1023u;

    const int t = blockIdx.x;
    const int tid = threadIdx.x;
    const int w = tid >> 5;
    const int l = tid & 31;

    if (tid == 0) {
        MBAR_INIT(sb + LG_CTL + 0, 1);
        MBAR_INIT(sb + LG_CTL + 8, 1);
        MBAR_INIT(sb + LG_CTL + 16, 8);
        MBAR_INIT(sb + LG_CTL + 24, 8);
    }
    __syncthreads();

    if (w == 8) {
        if (l == 0) {
            const char* asrc = (const char*)(g_hsf + (size_t)t * HF_T);
            const char* bsrc = (const char*)g_WcombF;
            for (int s = 0; s < 16; s++) {
                int k = s >> 1;
                if (s >= 2) MBAR_WAIT(sb + LG_CTL + 16 + (s & 1) * 8, (unsigned)((k - 1) & 1));
                MBAR_EXPECT_TX(sb + LG_CTL + (s & 1) * 8, 98304);
                BULK_CP(sb + LG_A + (s & 1) * 32768, asrc + s * 32768, 32768,
                        sb + LG_CTL + (s & 1) * 8);
                BULK_CP(sb + LG_B + (s & 1) * 65536, bsrc + s * 65536, 65536,
                        sb + LG_CTL + (s & 1) * 8);
            }
        }
        return;
    }

    float acc[32][4];
#pragma unroll
    for (int nb = 0; nb < 32; nb++)
#pragma unroll
        for (int q = 0; q < 4; q++) acc[nb][q] = 0.f;

    for (int s = 0; s < 16; s++) {
        MBAR_WAIT(sb + LG_CTL + (s & 1) * 8, (unsigned)((s >> 1) & 1));
        uint32_t abase = sb + LG_A + (s & 1) * 32768;
        uint32_t bbase = sb + LG_B + (s & 1) * 65536;
#pragma unroll 2
        for (int kbi = 0; kbi < 8; kbi++) {
            uint32_t a[4];
            LDS128(a, abase + (uint32_t)(kbi * 4096 + w * 512 + l * 16));
#pragma unroll
            for (int nb = 0; nb < 32; nb++) {
                uint32_t b0, b1;
                LDS64(b0, b1, bbase + (uint32_t)(kbi * 8192 + nb * 256 + l * 8));
                MMA_TF32(acc[nb], a, b0, b1);
            }
        }
        if (l == 0) MBAR_ARRIVE(sb + LG_CTL + 16 + (s & 1) * 8);
    }

    // bias + log_softmax (rows 16w+g and 16w+g+8; cols spread over quad lanes)
    int g = l >> 2, tig = l & 3;
    float mx0 = -1e30f, mx1 = -1e30f;
#pragma unroll
    for (int nb = 0; nb < 32; nb++) {
        float2 bc = *(const float2*)(g_bcomb + nb * 8 + 2 * tig);
        acc[nb][0] += bc.x; acc[nb][1] += bc.y;
        acc[nb][2] += bc.x; acc[nb][3] += bc.y;
        mx0 = fmaxf(mx0, fmaxf(acc[nb][0], acc[nb][1]));
        mx1 = fmaxf(mx1, fmaxf(acc[nb][2], acc[nb][3]));
    }
    mx0 = fmaxf(mx0, __shfl_xor_sync(0xffffffffu, mx0, 1));
    mx0 = fmaxf(mx0, __shfl_xor_sync(0xffffffffu, mx0, 2));
    mx1 = fmaxf(mx1, __shfl_xor_sync(0xffffffffu, mx1, 1));
    mx1 = fmaxf(mx1, __shfl_xor_sync(0xffffffffu, mx1, 2));
    float s0 = 0.f, s1 = 0.f;
#pragma unroll
    for (int nb = 0; nb < 32; nb++) {
        s0 += __expf(acc[nb][0] - mx0) + __expf(acc[nb][1] - mx0);
        s1 += __expf(acc[nb][2] - mx1) + __expf(acc[nb][3] - mx1);
    }
    s0 += __shfl_xor_sync(0xffffffffu, s0, 1);
    s0 += __shfl_xor_sync(0xffffffffu, s0, 2);
    s1 += __shfl_xor_sync(0xffffffffu, s1, 1);
    s1 += __shfl_xor_sync(0xffffffffu, s1, 2);
    float lse0 = mx0 + logf(s0);
    float lse1 = mx1 + logf(s1);

    int b0r = (w << 4) + g;
    float* d0 = out + ((size_t)b0r * TT + t) * 256 + 2 * tig;
    float* d1 = out + ((size_t)(b0r + 8) * TT + t) * 256 + 2 * tig;
#pragma unroll
    for (int nb = 0; nb < 32; nb++) {
        *(float2*)(d0 + nb * 8) = make_float2(acc[nb][0] - lse0, acc[nb][1] - lse0);
        *(float2*)(d1 + nb * 8) = make_float2(acc[nb][2] - lse1, acc[nb][3] - lse1);
    }
}

// ---------------------------------------------------------------------------------------
extern "C" void kernel_launch(void* const* d_in, const int* in_sizes, int n_in,
                              void* d_out, int out_size) {
    const int*   x        = (const int*)  d_in[0];
    const float* emb      = (const float*)d_in[1];
    const float* lstm_Wih = (const float*)d_in[2];
    const float* lstm_Whh = (const float*)d_in[3];
    const float* lstm_bih = (const float*)d_in[4];
    const float* lstm_bhh = (const float*)d_in[5];
    const float* Wd       = (const float*)d_in[6];
    const float* bd       = (const float*)d_in[7];
    const float* Wo       = (const float*)d_in[8];
    const float* bo       = (const float*)d_in[9];
    const float* s1_Wih   = (const float*)d_in[10];
    const float* s1_bih   = (const float*)d_in[11];
    const float* s1_bhh   = (const float*)d_in[12];
    const float* s1_Wd    = (const float*)d_in[13];
    const float* s1_bd    = (const float*)d_in[14];
    const float* s2_Wih   = (const float*)d_in[15];
    const float* s2_bih   = (const float*)d_in[16];
    const float* s2_bhh   = (const float*)d_in[17];
    const float* s2_Wd    = (const float*)d_in[18];
    const float* s2_bd    = (const float*)d_in[19];
    float* out = (float*)d_out;

    const int rnn_smem = SM_TOTAL + 1024;
    const int lg_smem  = LG_TOTAL + 1024;
    cudaFuncSetAttribute(rnn5_kernel, cudaFuncAttributeMaxDynamicSharedMemorySize, rnn_smem);
    cudaFuncSetAttribute(logits_kernel, cudaFuncAttributeMaxDynamicSharedMemorySize, lg_smem);

    senti_tab_kernel<<<1, 256>>>(emb, s1_Wih, s1_bih, s1_bhh, s1_Wd, s1_bd,
                                 s2_Wih, s2_bih, s2_bhh, s2_Wd, s2_bd);
    tab_kernel<<<VV, 256>>>(emb, lstm_Wih, lstm_bih, lstm_bhh);
    wcomb_kernel<<<VV, 256>>>(Wd, bd, Wo, bo);
    wpack_kernel<<<128, 256>>>();
    init_kernel<<<(HF_T + 255) / 256, 256>>>();

    rnn5_kernel<<<NCTA, 288, rnn_smem>>>(x, lstm_Whh);

    logits_kernel<<<TT, 288, lg_smem>>>(out);
}

// round 10
// speedup vs baseline: 1.2780x; 1.2780x over previous
#include <cuda_runtime.h>
#include <math.h>
#include <stdint.h>

// Problem constants
#define BB   128
#define TT   1024
#define VV   256
#define EE   128
#define HH   1024
#define DD   512
#define SS   5
#define G4H  4096
#define NCTA 128

// h-state in A-fragment layout: [t][kb 0..127][mt 0..7][lane 0..31][slot 0..3] floats
#define HF_T 131072

// rnn smem layout (byte offsets from 1024-aligned base)
#define SM_B   0               // B fragments: 128KB
#define SM_A   131072          // A stages: 2 x 32KB
#define SM_CS  196608          // C tile [128][36] floats
#define SM_CTL 215040          // full0 +0, full1 +8, free0 +16, free1 +24
#define SM_TOTAL (215040 + 64)

// logits smem layout
#define LG_A   0               // A stages: 2 x 32KB
#define LG_B   65536           // B stages: 2 x 64KB
#define LG_CTL 196608
#define LG_TOTAL (196608 + 64)

// ---------------- device scratch -------------------------------------------------------
__device__ float g_a2tab[VV * SS];
__device__ float g_gx_tab[VV * G4H];
__device__ float g_attn_tab[VV * G4H];
__device__ float g_Wcomb[VV * HH];
__device__ float g_bcomb[VV];
__device__ float g_h0f[HF_T];
__device__ float g_hsf[(size_t)TT * HF_T];
__device__ float2 g_WcombF[128 * 32 * 32];          // Wcomb B-fragments (1 MB)
__device__ unsigned g_count;
__device__ volatile unsigned g_gen;

__device__ __forceinline__ float sigm(float x) { return 1.0f / (1.0f + __expf(-x)); }
__device__ __forceinline__ uint32_t f2tf32(float f) {
    uint32_t u;
    asm("cvt.rna.tf32.f32 %0, %1;" : "=r"(u) : "f"(f));
    return u;
}
__device__ __forceinline__ uint32_t smem_u32(const void* p) {
    uint32_t a;
    asm("{ .reg .u64 t; cvta.to.shared.u64 t, %1; cvt.u32.u64 %0, t; }" : "=r"(a) : "l"(p));
    return a;
}

#define MBAR_INIT(a, n) asm volatile("mbarrier.init.shared.b64 [%0], %1;" :: "r"(a), "r"((uint32_t)(n)) : "memory")
#define MBAR_ARRIVE(a)  asm volatile("mbarrier.arrive.shared.b64 _, [%0];" :: "r"(a) : "memory")
#define MBAR_EXPECT_TX(a, b) asm volatile("mbarrier.arrive.expect_tx.shared.b64 _, [%0], %1;" :: "r"(a), "r"((uint32_t)(b)) : "memory")
#define MBAR_WAIT(a, par) do { \
    uint32_t _m = (a), _p = (par), _d; \
    asm volatile("{ .reg .pred p; mbarrier.try_wait.parity.acquire.cta.shared::cta.b64 p, [%1], %2; selp.b32 %0,1,0,p; }" \
                 : "=r"(_d) : "r"(_m), "r"(_p) : "memory"); \
    if (!_d) { \
        asm volatile("{ .reg .pred P1; WL_%=: mbarrier.try_wait.parity.acquire.cta.shared::cta.b64 P1, [%0], %1, 0x989680; " \
                     "@P1 bra.uni WD_%=; bra.uni WL_%=; WD_%=: }" :: "r"(_m), "r"(_p) : "memory"); \
    } } while (0)

#define BULK_CP(dst, src, bytes, mbar) \
    asm volatile("cp.async.bulk.shared::cluster.global.mbarrier::complete_tx::bytes [%0], [%1], %2, [%3];" \
                 :: "r"(dst), "l"(src), "r"((uint32_t)(bytes)), "r"(mbar) : "memory")

#define LDS128(r, addr) \
    asm volatile("ld.shared.v4.b32 {%0,%1,%2,%3}, [%4];" \
                 : "=r"((r)[0]), "=r"((r)[1]), "=r"((r)[2]), "=r"((r)[3]) : "r"(addr))
#define LDS64(r0, r1, addr) \
    asm volatile("ld.shared.v2.b32 {%0,%1}, [%2];" : "=r"(r0), "=r"(r1) : "r"(addr))

#define MMA_TF32(acc, a, b0, b1) \
    asm volatile("mma.sync.aligned.m16n8k8.row.col.f32.tf32.tf32.f32 " \
                 "{%0,%1,%2,%3}, {%4,%5,%6,%7}, {%8,%9}, {%0,%1,%2,%3};" \
                 : "+f"((acc)[0]), "+f"((acc)[1]), "+f"((acc)[2]), "+f"((acc)[3]) \
                 : "r"((a)[0]), "r"((a)[1]), "r"((a)[2]), "r"((a)[3]), "r"(b0), "r"(b1))

// ---------------- prep kernels ---------------------------------------------------------
__global__ void senti_tab_kernel(const float* __restrict__ emb,
                                 const float* __restrict__ s1_Wih, const float* __restrict__ s1_bih,
                                 const float* __restrict__ s1_bhh, const float* __restrict__ s1_Wd,
                                 const float* __restrict__ s1_bd,
                                 const float* __restrict__ s2_Wih, const float* __restrict__ s2_bih,
                                 const float* __restrict__ s2_bhh, const float* __restrict__ s2_Wd,
                                 const float* __restrict__ s2_bd) {
    int v = blockIdx.x * blockDim.x + threadIdx.x;
    if (v >= VV) return;
    float h1[8];
    {
        float g[32];
        const float* e = emb + v * EE;
        for (int j = 0; j < 32; j++) {
            const float* w = s1_Wih + j * EE;
            float a = s1_bih[j] + s1_bhh[j];
            for (int k = 0; k < EE; k++) a += e[k] * w[k];
            g[j] = a;
        }
        for (int u = 0; u < 8; u++) {
            float cc = sigm(g[u]) * tanhf(g[16 + u]);
            h1[u] = sigm(g[24 + u]) * tanhf(cc);
        }
    }
    float a1[SS];
    {
        float l[SS], m = -1e30f;
        for (int s = 0; s < SS; s++) {
            float a = s1_bd[s];
            for (int u = 0; u < 8; u++) a += h1[u] * s1_Wd[s * 8 + u];
            l[s] = a; m = fmaxf(m, a);
        }
        float sum = 0.0f;
        for (int s = 0; s < SS; s++) { l[s] = __expf(l[s] - m); sum += l[s]; }
        for (int s = 0; s < SS; s++) a1[s] = l[s] / sum;
    }
    float h2[8];
    {
        float g[32];
        for (int j = 0; j < 32; j++) {
            const float* w = s2_Wih + j * SS;
            float a = s2_bih[j] + s2_bhh[j];
            for (int s = 0; s < SS; s++) a += a1[s] * w[s];
            g[j] = a;
        }
        for (int u = 0; u < 8; u++) {
            float cc = sigm(g[u]) * tanhf(g[16 + u]);
            h2[u] = sigm(g[24 + u]) * tanhf(cc);
        }
    }
    {
        float l[SS], m = -1e30f;
        for (int s = 0; s < SS; s++) {
            float a = s2_bd[s];
            for (int u = 0; u < 8; u++) a += h2[u] * s2_Wd[s * 8 + u];
            l[s] = a; m = fmaxf(m, a);
        }
        float sum = 0.0f;
        for (int s = 0; s < SS; s++) { l[s] = __expf(l[s] - m); sum += l[s]; }
        for (int s = 0; s < SS; s++) g_a2tab[v * SS + s] = l[s] / sum;
    }
}

__global__ __launch_bounds__(256) void tab_kernel(const float* __restrict__ emb,
                                                  const float* __restrict__ Wih,
                                                  const float* __restrict__ bih,
                                                  const float* __restrict__ bhh) {
    int v = blockIdx.x;
    __shared__ float se[EE];
    __shared__ float sa[SS];
    if (threadIdx.x < EE) se[threadIdx.x] = emb[v * EE + threadIdx.x];
    if (threadIdx.x < SS) sa[threadIdx.x] = g_a2tab[v * SS + threadIdx.x];
    __syncthreads();
    for (int j = threadIdx.x; j < G4H; j += 256) {
        const float* w = Wih + (size_t)j * (EE + SS);
        float a = bih[j] + bhh[j];
        for (int k = 0; k < EE; k++) a += se[k] * w[k];
        g_gx_tab[v * G4H + j] = a;
        float at = 0.0f;
        for (int s = 0; s < SS; s++) at += sa[s] * w[EE + s];
        g_attn_tab[v * G4H + j] = at;
    }
}

__global__ __launch_bounds__(256) void wcomb_kernel(const float* __restrict__ Wd,
                                                    const float* __restrict__ bd,
                                                    const float* __restrict__ Wo,
                                                    const float* __restrict__ bo) {
    int o = blockIdx.x;
    __shared__ float swo[DD];
    for (int i = threadIdx.x; i < DD; i += 256) swo[i] = Wo[o * DD + i];
    __syncthreads();
    for (int k = threadIdx.x; k < HH; k += 256) {
        float a = 0.0f;
        for (int d = 0; d < DD; d++) a += swo[d] * Wd[d * HH + k];
        g_Wcomb[o * HH + k] = a;
    }
    if (threadIdx.x == 0) {
        float a = bo[o];
        for (int d = 0; d < DD; d++) a += swo[d] * bd[d];
        g_bcomb[o] = a;
    }
}

// pack Wcomb into B-fragment layout (tf32-rounded): [kb][nblk][lane] float2
__global__ __launch_bounds__(256) void wpack_kernel() {
    int kb = blockIdx.x;
    for (int i = threadIdx.x; i < 1024; i += 256) {
        int nb = i >> 5, L = i & 31;
        int o = nb * 8 + (L >> 2);
        int k = kb * 8 + (L & 3);
        float2 v;
        v.x = __uint_as_float(f2tf32(g_Wcomb[(size_t)o * HH + k]));
        v.y = __uint_as_float(f2tf32(g_Wcomb[(size_t)o * HH + k + 4]));
        g_WcombF[(kb * 32 + nb) * 32 + L] = v;
    }
}

__global__ void init_kernel() {
    int idx = blockIdx.x * blockDim.x + threadIdx.x;
    if (idx < HF_T) g_h0f[idx] = 0.0f;
    if (idx == 0) { g_count = 0; g_gen = 0; }
}

// ---------------- global software barrier ----------------------------------------------
__device__ __forceinline__ void gbar(unsigned target) {
    __syncthreads();
    if (threadIdx.x == 0) {
        __threadfence();
        unsigned prev = atomicAdd(&g_count, 1);
        if (prev == NCTA - 1) {
            g_count = 0;
            __threadfence();
            g_gen = target;
        } else {
            while (g_gen < target) __nanosleep(32);
        }
        __threadfence();
    }
    __syncthreads();
}

// ---------------- persistent recurrence: warp-specialized bulk-copy + tf32 mma ---------
// 128 CTAs x 256 thr. CTA jt owns cols c = gate*8+uu (Whh row j = gate*1024 + jt*8 + uu).
// Warps 0-3: MMA consumers, warp w owns rows 32w..32w+31.
// Thread 128: producer, 16 bulk copies of 32KB per step (A stages, double-buffered).
// Threads 129-255: prefetch gate tables during MMA phase.
// Warps 4-7: LSTM pointwise after sync (cell state in regs), h in fragment layout.
__global__ __launch_bounds__(256, 1) void rnn4_kernel(const int* __restrict__ x,
                                                      const float* __restrict__ Whh) {
    extern __shared__ char smraw[];
    uint32_t sb0 = smem_u32(smraw);
    uint32_t sb = (sb0 + 1023u) & ~1023u;
    char* smem = smraw + (sb - sb0);
    float* Cs = (float*)(smem + SM_CS);

    const int tid = threadIdx.x;
    const int jt  = blockIdx.x;
    const int w   = tid >> 5;
    const int l   = tid & 31;

    // ---- pack B fragments (tf32-rounded): [kb][np][lane] 16B ----
    {
        float4* Bp = (float4*)(smem + SM_B);
        for (int i = tid; i < 8192; i += 256) {
            int kb = i >> 6;
            int np = (i >> 5) & 1;
            int L  = i & 31;
            int tig = L & 3, g0 = L >> 2;
            int j0 = (2 * np) * 1024 + jt * 8 + g0;
            int j1 = j0 + 1024;
            int k0 = kb * 8 + tig;
            float4 v;
            v.x = __uint_as_float(f2tf32(Whh[(size_t)j0 * HH + k0]));
            v.y = __uint_as_float(f2tf32(Whh[(size_t)j0 * HH + k0 + 4]));
            v.z = __uint_as_float(f2tf32(Whh[(size_t)j1 * HH + k0]));
            v.w = __uint_as_float(f2tf32(Whh[(size_t)j1 * HH + k0 + 4]));
            Bp[i] = v;
        }
    }
    if (tid == 0) {
        MBAR_INIT(sb + SM_CTL + 0, 1);    // full buf0
        MBAR_INIT(sb + SM_CTL + 8, 1);    // full buf1
        MBAR_INIT(sb + SM_CTL + 16, 4);   // free buf0 (4 consumer warps)
        MBAR_INIT(sb + SM_CTL + 24, 4);   // free buf1
    }

    float creg[8] = {0.f, 0.f, 0.f, 0.f, 0.f, 0.f, 0.f, 0.f};
    float gadd[4][8];

    gbar(1);

    for (int t = 0; t < TT; t++) {
        if (w < 4) {
            // ================= MMA consumers =================
            float acc[2][4][4];
#pragma unroll
            for (int m = 0; m < 2; m++)
#pragma unroll
                for (int n = 0; n < 4; n++)
#pragma unroll
                    for (int q = 0; q < 4; q++) acc[m][n][q] = 0.f;

            for (int s = 0; s < 16; s++) {
                unsigned u = (unsigned)(t * 8 + (s >> 1));
                MBAR_WAIT(sb + SM_CTL + (s & 1) * 8, u & 1u);
                uint32_t abase = sb + SM_A + (s & 1) * 32768;
#pragma unroll
                for (int kbi = 0; kbi < 8; kbi++) {
                    int kb = s * 8 + kbi;
                    uint32_t aaddr = abase + (uint32_t)(((kbi * 8 + 2 * w) * 32 + l) * 16);
                    uint32_t baddr = sb + SM_B + (uint32_t)(((kb * 2) * 32 + l) * 16);
                    uint32_t a0[4], a1[4], b0[4], b1[4];
                    LDS128(a0, aaddr);
                    LDS128(a1, aaddr + 512);
                    LDS128(b0, baddr);
                    LDS128(b1, baddr + 512);
                    MMA_TF32(acc[0][0], a0, b0[0], b0[1]);
                    MMA_TF32(acc[0][1], a0, b0[2], b0[3]);
                    MMA_TF32(acc[0][2], a0, b1[0], b1[1]);
                    MMA_TF32(acc[0][3], a0, b1[2], b1[3]);
                    MMA_TF32(acc[1][0], a1, b0[0], b0[1]);
                    MMA_TF32(acc[1][1], a1, b0[2], b0[3]);
                    MMA_TF32(acc[1][2], a1, b1[0], b1[1]);
                    MMA_TF32(acc[1][3], a1, b1[2], b1[3]);
                }
                if (l == 0) MBAR_ARRIVE(sb + SM_CTL + 16 + (s & 1) * 8);
            }
            // write C tile
            int gID = l >> 2, tig = l & 3;
#pragma unroll
            for (int mtl = 0; mtl < 2; mtl++) {
                int rb = w * 32 + mtl * 16 + gID;
#pragma unroll
                for (int nb = 0; nb < 4; nb++) {
                    *(float2*)&Cs[rb * 36 + nb * 8 + 2 * tig] =
                        make_float2(acc[mtl][nb][0], acc[mtl][nb][1]);
                    *(float2*)&Cs[(rb + 8) * 36 + nb * 8 + 2 * tig] =
                        make_float2(acc[mtl][nb][2], acc[mtl][nb][3]);
                }
            }
        } else if (tid == 128) {
            // ================= producer: 16 bulk copies =================
            const float* src = t ? (g_hsf + (size_t)(t - 1) * HF_T) : g_h0f;
            for (int s = 0; s < 16; s++) {
                unsigned u = (unsigned)(t * 8 + (s >> 1));
                if (u > 0) MBAR_WAIT(sb + SM_CTL + 16 + (s & 1) * 8, (u - 1) & 1u);
                MBAR_EXPECT_TX(sb + SM_CTL + (s & 1) * 8, 32768);
                BULK_CP(sb + SM_A + (s & 1) * 32768, src + s * 8192, 32768,
                        sb + SM_CTL + (s & 1) * 8);
            }
        } else {
            // ================= threads 129-255: prefetch gate tables =========
            int b = tid - 128;
            int tok = __ldg(&x[b * TT + t]);
            const float* gx = g_gx_tab + (size_t)tok * G4H + (jt << 3);
#pragma unroll
            for (int gate = 0; gate < 4; gate++) {
                float4 p0 = *(const float4*)(gx + (gate << 10));
                float4 p1 = *(const float4*)(gx + (gate << 10) + 4);
                gadd[gate][0] = p0.x; gadd[gate][1] = p0.y; gadd[gate][2] = p0.z; gadd[gate][3] = p0.w;
                gadd[gate][4] = p1.x; gadd[gate][5] = p1.y; gadd[gate][6] = p1.z; gadd[gate][7] = p1.w;
            }
            if (t > 0) {
                int pt = __ldg(&x[b * TT + t - 1]);
                const float* at = g_attn_tab + (size_t)pt * G4H + (jt << 3);
#pragma unroll
                for (int gate = 0; gate < 4; gate++) {
                    float4 p0 = *(const float4*)(at + (gate << 10));
                    float4 p1 = *(const float4*)(at + (gate << 10) + 4);
                    gadd[gate][0] += p0.x; gadd[gate][1] += p0.y; gadd[gate][2] += p0.z; gadd[gate][3] += p0.w;
                    gadd[gate][4] += p1.x; gadd[gate][5] += p1.y; gadd[gate][6] += p1.z; gadd[gate][7] += p1.w;
                }
            }
        }
        __syncthreads();

        // ================= pointwise (warps 4-7): thread b = tid-128 ================
        if (w >= 4) {
            int b = tid - 128;
            if (b == 0) {
                // thread 128 was producing; load its tables now
                int tok = __ldg(&x[b * TT + t]);
                const float* gx = g_gx_tab + (size_t)tok * G4H + (jt << 3);
#pragma unroll
                for (int gate = 0; gate < 4; gate++) {
                    float4 p0 = *(const float4*)(gx + (gate << 10));
                    float4 p1 = *(const float4*)(gx + (gate << 10) + 4);
                    gadd[gate][0] = p0.x; gadd[gate][1] = p0.y; gadd[gate][2] = p0.z; gadd[gate][3] = p0.w;
                    gadd[gate][4] = p1.x; gadd[gate][5] = p1.y; gadd[gate][6] = p1.z; gadd[gate][7] = p1.w;
                }
                if (t > 0) {
                    int pt = __ldg(&x[b * TT + t - 1]);
                    const float* at = g_attn_tab + (size_t)pt * G4H + (jt << 3);
#pragma unroll
                    for (int gate = 0; gate < 4; gate++) {
                        float4 p0 = *(const float4*)(at + (gate << 10));
                        float4 p1 = *(const float4*)(at + (gate << 10) + 4);
                        gadd[gate][0] += p0.x; gadd[gate][1] += p0.y; gadd[gate][2] += p0.z; gadd[gate][3] += p0.w;
                        gadd[gate][4] += p1.x; gadd[gate][5] += p1.y; gadd[gate][6] += p1.z; gadd[gate][7] += p1.w;
                    }
                }
            }
            int mt = b >> 4, ri = b & 15;
            float* hdst = g_hsf + ((size_t)t * 128 + jt) * 1024 + mt * 128;
#pragma unroll
            for (int uu = 0; uu < 8; uu++) {
                float gi = Cs[b * 36 + uu]      + gadd[0][uu];
                float gf = Cs[b * 36 + 8 + uu]  + gadd[1][uu];
                float gg = Cs[b * 36 + 16 + uu] + gadd[2][uu];
                float go = Cs[b * 36 + 24 + uu] + gadd[3][uu];
                float cn = sigm(gf) * creg[uu] + sigm(gi) * tanhf(gg);
                float hn = sigm(go) * tanhf(cn);
                creg[uu] = cn;
                int L = (ri & 7) * 4 + (uu & 3);
                int slot = ((uu >= 4) ? 2 : 0) + ((ri >= 8) ? 1 : 0);
                hdst[L * 4 + slot] = __uint_as_float(f2tf32(hn));
            }
            __threadfence();
        }

        gbar((unsigned)(t + 2));
    }
}

// ---------------- epilogue: tf32 MMA logits + log_softmax ------------------------------
// 1024 CTAs (one per t) x 288 thr. Warps 0-7: m16 rows each, all 256 cols.
// Warp 8 lane 0: bulk-copy producer (A chunk 32KB + B chunk 64KB per stage).
__global__ __launch_bounds__(288, 1) void logits_kernel(float* __restrict__ out) {
    extern __shared__ char smraw[];
    uint32_t sb0 = smem_u32(smraw);
    uint32_t sb = (sb0 + 1023u) & ~1023u;

    const int t = blockIdx.x;
    const int tid = threadIdx.x;
    const int w = tid >> 5;
    const int l = tid & 31;

    if (tid == 0) {
        MBAR_INIT(sb + LG_CTL + 0, 1);
        MBAR_INIT(sb + LG_CTL + 8, 1);
        MBAR_INIT(sb + LG_CTL + 16, 8);
        MBAR_INIT(sb + LG_CTL + 24, 8);
    }
    __syncthreads();

    if (w == 8) {
        if (l == 0) {
            const char* asrc = (const char*)(g_hsf + (size_t)t * HF_T);
            const char* bsrc = (const char*)g_WcombF;
            for (int s = 0; s < 16; s++) {
                int k = s >> 1;
                if (s >= 2) MBAR_WAIT(sb + LG_CTL + 16 + (s & 1) * 8, (unsigned)((k - 1) & 1));
                MBAR_EXPECT_TX(sb + LG_CTL + (s & 1) * 8, 98304);
                BULK_CP(sb + LG_A + (s & 1) * 32768, asrc + s * 32768, 32768,
                        sb + LG_CTL + (s & 1) * 8);
                BULK_CP(sb + LG_B + (s & 1) * 65536, bsrc + s * 65536, 65536,
                        sb + LG_CTL + (s & 1) * 8);
            }
        }
        return;
    }

    float acc[32][4];
#pragma unroll
    for (int nb = 0; nb < 32; nb++)
#pragma unroll
        for (int q = 0; q < 4; q++) acc[nb][q] = 0.f;

    for (int s = 0; s < 16; s++) {
        MBAR_WAIT(sb + LG_CTL + (s & 1) * 8, (unsigned)((s >> 1) & 1));
        uint32_t abase = sb + LG_A + (s & 1) * 32768;
        uint32_t bbase = sb + LG_B + (s & 1) * 65536;
#pragma unroll 2
        for (int kbi = 0; kbi < 8; kbi++) {
            uint32_t a[4];
            LDS128(a, abase + (uint32_t)(kbi * 4096 + w * 512 + l * 16));
#pragma unroll
            for (int nb = 0; nb < 32; nb++) {
                uint32_t b0, b1;
                LDS64(b0, b1, bbase + (uint32_t)(kbi * 8192 + nb * 256 + l * 8));
                MMA_TF32(acc[nb], a, b0, b1);
            }
        }
        if (l == 0) MBAR_ARRIVE(sb + LG_CTL + 16 + (s & 1) * 8);
    }

    // bias + log_softmax (rows 16w+g and 16w+g+8; cols spread over quad lanes)
    int g = l >> 2, tig = l & 3;
    float mx0 = -1e30f, mx1 = -1e30f;
#pragma unroll
    for (int nb = 0; nb < 32; nb++) {
        float2 bc = *(const float2*)(g_bcomb + nb * 8 + 2 * tig);
        acc[nb][0] += bc.x; acc[nb][1] += bc.y;
        acc[nb][2] += bc.x; acc[nb][3] += bc.y;
        mx0 = fmaxf(mx0, fmaxf(acc[nb][0], acc[nb][1]));
        mx1 = fmaxf(mx1, fmaxf(acc[nb][2], acc[nb][3]));
    }
    mx0 = fmaxf(mx0, __shfl_xor_sync(0xffffffffu, mx0, 1));
    mx0 = fmaxf(mx0, __shfl_xor_sync(0xffffffffu, mx0, 2));
    mx1 = fmaxf(mx1, __shfl_xor_sync(0xffffffffu, mx1, 1));
    mx1 = fmaxf(mx1, __shfl_xor_sync(0xffffffffu, mx1, 2));
    float s0 = 0.f, s1 = 0.f;
#pragma unroll
    for (int nb = 0; nb < 32; nb++) {
        s0 += __expf(acc[nb][0] - mx0) + __expf(acc[nb][1] - mx0);
        s1 += __expf(acc[nb][2] - mx1) + __expf(acc[nb][3] - mx1);
    }
    s0 += __shfl_xor_sync(0xffffffffu, s0, 1);
    s0 += __shfl_xor_sync(0xffffffffu, s0, 2);
    s1 += __shfl_xor_sync(0xffffffffu, s1, 1);
    s1 += __shfl_xor_sync(0xffffffffu, s1, 2);
    float lse0 = mx0 + logf(s0);
    float lse1 = mx1 + logf(s1);

    int b0r = (w << 4) + g;
    float* d0 = out + ((size_t)b0r * TT + t) * 256 + 2 * tig;
    float* d1 = out + ((size_t)(b0r + 8) * TT + t) * 256 + 2 * tig;
#pragma unroll
    for (int nb = 0; nb < 32; nb++) {
        *(float2*)(d0 + nb * 8) = make_float2(acc[nb][0] - lse0, acc[nb][1] - lse0);
        *(float2*)(d1 + nb * 8) = make_float2(acc[nb][2] - lse1, acc[nb][3] - lse1);
    }
}

// ---------------------------------------------------------------------------------------
extern "C" void kernel_launch(void* const* d_in, const int* in_sizes, int n_in,
                              void* d_out, int out_size) {
    const int*   x        = (const int*)  d_in[0];
    const float* emb      = (const float*)d_in[1];
    const float* lstm_Wih = (const float*)d_in[2];
    const float* lstm_Whh = (const float*)d_in[3];
    const float* lstm_bih = (const float*)d_in[4];
    const float* lstm_bhh = (const float*)d_in[5];
    const float* Wd       = (const float*)d_in[6];
    const float* bd       = (const float*)d_in[7];
    const float* Wo       = (const float*)d_in[8];
    const float* bo       = (const float*)d_in[9];
    const float* s1_Wih   = (const float*)d_in[10];
    const float* s1_bih   = (const float*)d_in[11];
    const float* s1_bhh   = (const float*)d_in[12];
    const float* s1_Wd    = (const float*)d_in[13];
    const float* s1_bd    = (const float*)d_in[14];
    const float* s2_Wih   = (const float*)d_in[15];
    const float* s2_bih   = (const float*)d_in[16];
    const float* s2_bhh   = (const float*)d_in[17];
    const float* s2_Wd    = (const float*)d_in[18];
    const float* s2_bd    = (const float*)d_in[19];
    float* out = (float*)d_out;

    const int rnn_smem = SM_TOTAL + 1024;
    const int lg_smem  = LG_TOTAL + 1024;
    cudaFuncSetAttribute(rnn4_kernel, cudaFuncAttributeMaxDynamicSharedMemorySize, rnn_smem);
    cudaFuncSetAttribute(logits_kernel, cudaFuncAttributeMaxDynamicSharedMemorySize, lg_smem);

    senti_tab_kernel<<<1, 256>>>(emb, s1_Wih, s1_bih, s1_bhh, s1_Wd, s1_bd,
                                 s2_Wih, s2_bih, s2_bhh, s2_Wd, s2_bd);
    tab_kernel<<<VV, 256>>>(emb, lstm_Wih, lstm_bih, lstm_bhh);
    wcomb_kernel<<<VV, 256>>>(Wd, bd, Wo, bo);
    wpack_kernel<<<128, 256>>>();
    init_kernel<<<(HF_T + 255) / 256, 256>>>();

    rnn4_kernel<<<NCTA, 256, rnn_smem>>>(x, lstm_Whh);

    logits_kernel<<<TT, 288, lg_smem>>>(out);
}

// round 12
// speedup vs baseline: 1.5106x; 1.1820x over previous
#include <cuda_runtime.h>
#include <math.h>
#include <stdint.h>

// Problem constants
#define BB   128
#define TT   1024
#define VV   256
#define EE   128
#define HH   1024
#define DD   512
#define SS   5
#define G4H  4096
#define NCTA 128

// h-state in A-fragment layout: [t][kb 0..127][mt 0..7][lane 0..31][slot 0..3] floats
#define HF_T 131072

// rnn smem layout (byte offsets from 1024-aligned base)
#define SM_B   0               // B fragments: 128KB
#define SM_A   131072          // A stages: 2 x 32KB
#define SM_CS  196608          // C tile [128][36] floats
#define SM_CTL 215040          // full0 +0, full1 +8, free0 +16, free1 +24
#define SM_TOTAL (215040 + 64)

// logits smem layout
#define LG_A   0               // A stages: 2 x 32KB
#define LG_B   65536           // B stages: 2 x 64KB
#define LG_CTL 196608
#define LG_TOTAL (196608 + 64)

// ---------------- device scratch -------------------------------------------------------
__device__ float g_a2tab[VV * SS];
__device__ float g_gx_tab[VV * G4H];
__device__ float g_attn_tab[VV * G4H];
__device__ float g_Wcomb[VV * HH];
__device__ float g_bcomb[VV];
__device__ float g_h0f[HF_T];
__device__ float g_hsf[(size_t)TT * HF_T];
__device__ float2 g_WcombF[128 * 32 * 32];          // Wcomb B-fragments (1 MB)
__device__ int   g_done[TT];                        // per-step completion counters

__device__ __forceinline__ float sigm(float x) { return 1.0f / (1.0f + __expf(-x)); }
__device__ __forceinline__ uint32_t f2tf32(float f) {
    uint32_t u;
    asm("cvt.rna.tf32.f32 %0, %1;" : "=r"(u) : "f"(f));
    return u;
}
__device__ __forceinline__ uint32_t smem_u32(const void* p) {
    uint32_t a;
    asm("{ .reg .u64 t; cvta.to.shared.u64 t, %1; cvt.u32.u64 %0, t; }" : "=r"(a) : "l"(p));
    return a;
}

#define MBAR_INIT(a, n) asm volatile("mbarrier.init.shared.b64 [%0], %1;" :: "r"(a), "r"((uint32_t)(n)) : "memory")
#define MBAR_ARRIVE(a)  asm volatile("mbarrier.arrive.shared.b64 _, [%0];" :: "r"(a) : "memory")
#define MBAR_EXPECT_TX(a, b) asm volatile("mbarrier.arrive.expect_tx.shared.b64 _, [%0], %1;" :: "r"(a), "r"((uint32_t)(b)) : "memory")
#define MBAR_WAIT(a, par) do { \
    uint32_t _m = (a), _p = (par), _d; \
    asm volatile("{ .reg .pred p; mbarrier.try_wait.parity.acquire.cta.shared::cta.b64 p, [%1], %2; selp.b32 %0,1,0,p; }" \
                 : "=r"(_d) : "r"(_m), "r"(_p) : "memory"); \
    if (!_d) { \
        asm volatile("{ .reg .pred P1; WL_%=: mbarrier.try_wait.parity.acquire.cta.shared::cta.b64 P1, [%0], %1, 0x989680; " \
                     "@P1 bra.uni WD_%=; bra.uni WL_%=; WD_%=: }" :: "r"(_m), "r"(_p) : "memory"); \
    } } while (0)

#define BULK_CP(dst, src, bytes, mbar) \
    asm volatile("cp.async.bulk.shared::cluster.global.mbarrier::complete_tx::bytes [%0], [%1], %2, [%3];" \
                 :: "r"(dst), "l"(src), "r"((uint32_t)(bytes)), "r"(mbar) : "memory")

#define LDS128(r, addr) \
    asm volatile("ld.shared.v4.b32 {%0,%1,%2,%3}, [%4];" \
                 : "=r"((r)[0]), "=r"((r)[1]), "=r"((r)[2]), "=r"((r)[3]) : "r"(addr))
#define LDS64(r0, r1, addr) \
    asm volatile("ld.shared.v2.b32 {%0,%1}, [%2];" : "=r"(r0), "=r"(r1) : "r"(addr))

#define MMA_TF32(acc, a, b0, b1) \
    asm volatile("mma.sync.aligned.m16n8k8.row.col.f32.tf32.tf32.f32 " \
                 "{%0,%1,%2,%3}, {%4,%5,%6,%7}, {%8,%9}, {%0,%1,%2,%3};" \
                 : "+f"((acc)[0]), "+f"((acc)[1]), "+f"((acc)[2]), "+f"((acc)[3]) \
                 : "r"((a)[0]), "r"((a)[1]), "r"((a)[2]), "r"((a)[3]), "r"(b0), "r"(b1))

// ---------------- prep kernels ---------------------------------------------------------
__global__ void senti_tab_kernel(const float* __restrict__ emb,
                                 const float* __restrict__ s1_Wih, const float* __restrict__ s1_bih,
                                 const float* __restrict__ s1_bhh, const float* __restrict__ s1_Wd,
                                 const float* __restrict__ s1_bd,
                                 const float* __restrict__ s2_Wih, const float* __restrict__ s2_bih,
                                 const float* __restrict__ s2_bhh, const float* __restrict__ s2_Wd,
                                 const float* __restrict__ s2_bd) {
    int v = blockIdx.x * blockDim.x + threadIdx.x;
    if (v >= VV) return;
    float h1[8];
    {
        float g[32];
        const float* e = emb + v * EE;
        for (int j = 0; j < 32; j++) {
            const float* w = s1_Wih + j * EE;
            float a = s1_bih[j] + s1_bhh[j];
            for (int k = 0; k < EE; k++) a += e[k] * w[k];
            g[j] = a;
        }
        for (int u = 0; u < 8; u++) {
            float cc = sigm(g[u]) * tanhf(g[16 + u]);
            h1[u] = sigm(g[24 + u]) * tanhf(cc);
        }
    }
    float a1[SS];
    {
        float l[SS], m = -1e30f;
        for (int s = 0; s < SS; s++) {
            float a = s1_bd[s];
            for (int u = 0; u < 8; u++) a += h1[u] * s1_Wd[s * 8 + u];
            l[s] = a; m = fmaxf(m, a);
        }
        float sum = 0.0f;
        for (int s = 0; s < SS; s++) { l[s] = __expf(l[s] - m); sum += l[s]; }
        for (int s = 0; s < SS; s++) a1[s] = l[s] / sum;
    }
    float h2[8];
    {
        float g[32];
        for (int j = 0; j < 32; j++) {
            const float* w = s2_Wih + j * SS;
            float a = s2_bih[j] + s2_bhh[j];
            for (int s = 0; s < SS; s++) a += a1[s] * w[s];
            g[j] = a;
        }
        for (int u = 0; u < 8; u++) {
            float cc = sigm(g[u]) * tanhf(g[16 + u]);
            h2[u] = sigm(g[24 + u]) * tanhf(cc);
        }
    }
    {
        float l[SS], m = -1e30f;
        for (int s = 0; s < SS; s++) {
            float a = s2_bd[s];
            for (int u = 0; u < 8; u++) a += h2[u] * s2_Wd[s * 8 + u];
            l[s] = a; m = fmaxf(m, a);
        }
        float sum = 0.0f;
        for (int s = 0; s < SS; s++) { l[s] = __expf(l[s] - m); sum += l[s]; }
        for (int s = 0; s < SS; s++) g_a2tab[v * SS + s] = l[s] / sum;
    }
}

__global__ __launch_bounds__(256) void tab_kernel(const float* __restrict__ emb,
                                                  const float* __restrict__ Wih,
                                                  const float* __restrict__ bih,
                                                  const float* __restrict__ bhh) {
    int v = blockIdx.x;
    __shared__ float se[EE];
    __shared__ float sa[SS];
    if (threadIdx.x < EE) se[threadIdx.x] = emb[v * EE + threadIdx.x];
    if (threadIdx.x < SS) sa[threadIdx.x] = g_a2tab[v * SS + threadIdx.x];
    __syncthreads();
    for (int j = threadIdx.x; j < G4H; j += 256) {
        const float* w = Wih + (size_t)j * (EE + SS);
        float a = bih[j] + bhh[j];
        for (int k = 0; k < EE; k++) a += se[k] * w[k];
        g_gx_tab[v * G4H + j] = a;
        float at = 0.0f;
        for (int s = 0; s < SS; s++) at += sa[s] * w[EE + s];
        g_attn_tab[v * G4H + j] = at;
    }
}

__global__ __launch_bounds__(256) void wcomb_kernel(const float* __restrict__ Wd,
                                                    const float* __restrict__ bd,
                                                    const float* __restrict__ Wo,
                                                    const float* __restrict__ bo) {
    int o = blockIdx.x;
    __shared__ float swo[DD];
    for (int i = threadIdx.x; i < DD; i += 256) swo[i] = Wo[o * DD + i];
    __syncthreads();
    for (int k = threadIdx.x; k < HH; k += 256) {
        float a = 0.0f;
        for (int d = 0; d < DD; d++) a += swo[d] * Wd[d * HH + k];
        g_Wcomb[o * HH + k] = a;
    }
    if (threadIdx.x == 0) {
        float a = bo[o];
        for (int d = 0; d < DD; d++) a += swo[d] * bd[d];
        g_bcomb[o] = a;
    }
}

// pack Wcomb into B-fragment layout (tf32-rounded): [kb][nblk][lane] float2
__global__ __launch_bounds__(256) void wpack_kernel() {
    int kb = blockIdx.x;
    for (int i = threadIdx.x; i < 1024; i += 256) {
        int nb = i >> 5, L = i & 31;
        int o = nb * 8 + (L >> 2);
        int k = kb * 8 + (L & 3);
        float2 v;
        v.x = __uint_as_float(f2tf32(g_Wcomb[(size_t)o * HH + k]));
        v.y = __uint_as_float(f2tf32(g_Wcomb[(size_t)o * HH + k + 4]));
        g_WcombF[(kb * 32 + nb) * 32 + L] = v;
    }
}

__global__ void init_kernel() {
    int idx = blockIdx.x * blockDim.x + threadIdx.x;
    if (idx < HF_T) g_h0f[idx] = 0.0f;
    if (idx < TT) g_done[idx] = 0;
}

// ---------------- persistent recurrence: dataflow producer, no global barrier ----------
// 128 CTAs x 288 thr. CTA jt owns cols c = gate*8+uu (Whh row j = gate*1024 + jt*8 + uu).
// Warps 0-3: MMA consumers (m32 rows each).
// Warps 4-7: LSTM pointwise (thread b = tid-128); after h stores: fence -> bar2 ->
//            single atomicAdd(g_done[t]).
// Warp 8 lane 0: producer; per step polls g_done[t-1]==128 ONCE, then 16 bulk copies.
__global__ __launch_bounds__(288, 1) void rnn6_kernel(const int* __restrict__ x,
                                                      const float* __restrict__ Whh) {
    extern __shared__ char smraw[];
    uint32_t sb0 = smem_u32(smraw);
    uint32_t sb = (sb0 + 1023u) & ~1023u;
    char* smem = smraw + (sb - sb0);
    float* Cs = (float*)(smem + SM_CS);

    const int tid = threadIdx.x;
    const int jt  = blockIdx.x;
    const int w   = tid >> 5;
    const int l   = tid & 31;

    // ---- pack B fragments (tf32-rounded): [kb][np][lane] 16B ----
    {
        float4* Bp = (float4*)(smem + SM_B);
        for (int i = tid; i < 8192; i += 288) {
            int kb = i >> 6;
            int np = (i >> 5) & 1;
            int L  = i & 31;
            int tig = L & 3, g0 = L >> 2;
            int j0 = (2 * np) * 1024 + jt * 8 + g0;
            int j1 = j0 + 1024;
            int k0 = kb * 8 + tig;
            float4 v;
            v.x = __uint_as_float(f2tf32(Whh[(size_t)j0 * HH + k0]));
            v.y = __uint_as_float(f2tf32(Whh[(size_t)j0 * HH + k0 + 4]));
            v.z = __uint_as_float(f2tf32(Whh[(size_t)j1 * HH + k0]));
            v.w = __uint_as_float(f2tf32(Whh[(size_t)j1 * HH + k0 + 4]));
            Bp[i] = v;
        }
    }
    if (tid == 0) {
        MBAR_INIT(sb + SM_CTL + 0, 1);    // full buf0
        MBAR_INIT(sb + SM_CTL + 8, 1);    // full buf1
        MBAR_INIT(sb + SM_CTL + 16, 4);   // free buf0 (4 consumer warps)
        MBAR_INIT(sb + SM_CTL + 24, 4);   // free buf1
    }
    __syncthreads();

    // =========================== producer warp ===========================
    if (w == 8) {
        if (l != 0) return;
        for (int t = 0; t < TT; t++) {
            const float* src;
            if (t == 0) {
                src = g_h0f;
            } else {
                src = g_hsf + (size_t)(t - 1) * HF_T;
                int v;
                do {
                    asm volatile("ld.global.cg.b32 %0, [%1];" : "=r"(v) : "l"(g_done + (t - 1)) : "memory");
                    if (v >= NCTA) break;
                    __nanosleep(32);
                } while (1);
                __threadfence();
            }
            for (int s = 0; s < 16; s++) {
                unsigned u = (unsigned)(t * 8 + (s >> 1));
                if (u > 0) MBAR_WAIT(sb + SM_CTL + 16 + (s & 1) * 8, (u - 1) & 1u);
                MBAR_EXPECT_TX(sb + SM_CTL + (s & 1) * 8, 32768);
                BULK_CP(sb + SM_A + (s & 1) * 32768, src + s * 8192, 32768,
                        sb + SM_CTL + (s & 1) * 8);
            }
        }
        return;
    }

    // =========================== consumer warps ===========================
    if (w < 4) {
        for (int t = 0; t < TT; t++) {
            float acc[2][4][4];
#pragma unroll
            for (int m = 0; m < 2; m++)
#pragma unroll
                for (int n = 0; n < 4; n++)
#pragma unroll
                    for (int q = 0; q < 4; q++) acc[m][n][q] = 0.f;

            for (int s = 0; s < 16; s++) {
                unsigned u = (unsigned)(t * 8 + (s >> 1));
                MBAR_WAIT(sb + SM_CTL + (s & 1) * 8, u & 1u);
                uint32_t abase = sb + SM_A + (s & 1) * 32768;
#pragma unroll
                for (int kbi = 0; kbi < 8; kbi++) {
                    int kb = s * 8 + kbi;
                    uint32_t aaddr = abase + (uint32_t)(((kbi * 8 + 2 * w) * 32 + l) * 16);
                    uint32_t baddr = sb + SM_B + (uint32_t)(((kb * 2) * 32 + l) * 16);
                    uint32_t a0[4], a1[4], b0[4], b1[4];
                    LDS128(a0, aaddr);
                    LDS128(a1, aaddr + 512);
                    LDS128(b0, baddr);
                    LDS128(b1, baddr + 512);
                    MMA_TF32(acc[0][0], a0, b0[0], b0[1]);
                    MMA_TF32(acc[0][1], a0, b0[2], b0[3]);
                    MMA_TF32(acc[0][2], a0, b1[0], b1[1]);
                    MMA_TF32(acc[0][3], a0, b1[2], b1[3]);
                    MMA_TF32(acc[1][0], a1, b0[0], b0[1]);
                    MMA_TF32(acc[1][1], a1, b0[2], b0[3]);
                    MMA_TF32(acc[1][2], a1, b1[0], b1[1]);
                    MMA_TF32(acc[1][3], a1, b1[2], b1[3]);
                }
                if (l == 0) MBAR_ARRIVE(sb + SM_CTL + 16 + (s & 1) * 8);
            }
            // write C tile
            int gID = l >> 2, tig = l & 3;
#pragma unroll
            for (int mtl = 0; mtl < 2; mtl++) {
                int rb = w * 32 + mtl * 16 + gID;
#pragma unroll
                for (int nb = 0; nb < 4; nb++) {
                    *(float2*)&Cs[rb * 36 + nb * 8 + 2 * tig] =
                        make_float2(acc[mtl][nb][0], acc[mtl][nb][1]);
                    *(float2*)&Cs[(rb + 8) * 36 + nb * 8 + 2 * tig] =
                        make_float2(acc[mtl][nb][2], acc[mtl][nb][3]);
                }
            }
            asm volatile("bar.sync 1, 256;" ::: "memory");   // hand C to pointwise
        }
        return;
    }

    // =========================== pointwise warps (4-7) ===========================
    {
        const int b = tid - 128;
        float creg[8] = {0.f, 0.f, 0.f, 0.f, 0.f, 0.f, 0.f, 0.f};
        const int mt = b >> 4, ri = b & 15;

        for (int t = 0; t < TT; t++) {
            // prefetch gate tables while consumers run MMA
            float gadd[4][8];
            int tok = __ldg(&x[b * TT + t]);
            const float* gx = g_gx_tab + (size_t)tok * G4H + (jt << 3);
#pragma unroll
            for (int gate = 0; gate < 4; gate++) {
                float4 p0 = *(const float4*)(gx + (gate << 10));
                float4 p1 = *(const float4*)(gx + (gate << 10) + 4);
                gadd[gate][0] = p0.x; gadd[gate][1] = p0.y; gadd[gate][2] = p0.z; gadd[gate][3] = p0.w;
                gadd[gate][4] = p1.x; gadd[gate][5] = p1.y; gadd[gate][6] = p1.z; gadd[gate][7] = p1.w;
            }
            if (t > 0) {
                int pt = __ldg(&x[b * TT + t - 1]);
                const float* at = g_attn_tab + (size_t)pt * G4H + (jt << 3);
#pragma unroll
                for (int gate = 0; gate < 4; gate++) {
                    float4 p0 = *(const float4*)(at + (gate << 10));
                    float4 p1 = *(const float4*)(at + (gate << 10) + 4);
                    gadd[gate][0] += p0.x; gadd[gate][1] += p0.y; gadd[gate][2] += p0.z; gadd[gate][3] += p0.w;
                    gadd[gate][4] += p1.x; gadd[gate][5] += p1.y; gadd[gate][6] += p1.z; gadd[gate][7] += p1.w;
                }
            }

            asm volatile("bar.sync 1, 256;" ::: "memory");   // wait for C tile

            float* hdst = g_hsf + ((size_t)t * 128 + jt) * 1024 + mt * 128;
#pragma unroll
            for (int uu = 0; uu < 8; uu++) {
                float gi = Cs[b * 36 + uu]      + gadd[0][uu];
                float gf = Cs[b * 36 + 8 + uu]  + gadd[1][uu];
                float gg = Cs[b * 36 + 16 + uu] + gadd[2][uu];
                float go = Cs[b * 36 + 24 + uu] + gadd[3][uu];
                float cn = sigm(gf) * creg[uu] + sigm(gi) * tanhf(gg);
                float hn = sigm(go) * tanhf(cn);
                creg[uu] = cn;
                int L = (ri & 7) * 4 + (uu & 3);
                int slot = ((uu >= 4) ? 2 : 0) + ((ri >= 8) ? 1 : 0);
                hdst[L * 4 + slot] = __uint_as_float(f2tf32(hn));
            }
            __threadfence();
            asm volatile("bar.sync 2, 128;" ::: "memory");   // all h stores fenced
            if (b == 0) atomicAdd(&g_done[t], 1);
        }
    }
}

// ---------------- epilogue: tf32 MMA logits + log_softmax ------------------------------
// 1024 CTAs (one per t) x 288 thr. Warps 0-7: m16 rows each, all 256 cols.
// Warp 8 lane 0: bulk-copy producer (A chunk 32KB + B chunk 64KB per stage).
__global__ __launch_bounds__(288, 1) void logits_kernel(float* __restrict__ out) {
    extern __shared__ char smraw[];
    uint32_t sb0 = smem_u32(smraw);
    uint32_t sb = (sb0 + 1023u) & ~1023u;

    const int t = blockIdx.x;
    const int tid = threadIdx.x;
    const int w = tid >> 5;
    const int l = tid & 31;

    if (tid == 0) {
        MBAR_INIT(sb + LG_CTL + 0, 1);
        MBAR_INIT(sb + LG_CTL + 8, 1);
        MBAR_INIT(sb + LG_CTL + 16, 8);
        MBAR_INIT(sb + LG_CTL + 24, 8);
    }
    __syncthreads();

    if (w == 8) {
        if (l == 0) {
            const char* asrc = (const char*)(g_hsf + (size_t)t * HF_T);
            const char* bsrc = (const char*)g_WcombF;
            for (int s = 0; s < 16; s++) {
                int k = s >> 1;
                if (s >= 2) MBAR_WAIT(sb + LG_CTL + 16 + (s & 1) * 8, (unsigned)((k - 1) & 1));
                MBAR_EXPECT_TX(sb + LG_CTL + (s & 1) * 8, 98304);
                BULK_CP(sb + LG_A + (s & 1) * 32768, asrc + s * 32768, 32768,
                        sb + LG_CTL + (s & 1) * 8);
                BULK_CP(sb + LG_B + (s & 1) * 65536, bsrc + s * 65536, 65536,
                        sb + LG_CTL + (s & 1) * 8);
            }
        }
        return;
    }

    float acc[32][4];
#pragma unroll
    for (int nb = 0; nb < 32; nb++)
#pragma unroll
        for (int q = 0; q < 4; q++) acc[nb][q] = 0.f;

    for (int s = 0; s < 16; s++) {
        MBAR_WAIT(sb + LG_CTL + (s & 1) * 8, (unsigned)((s >> 1) & 1));
        uint32_t abase = sb + LG_A + (s & 1) * 32768;
        uint32_t bbase = sb + LG_B + (s & 1) * 65536;
#pragma unroll 2
        for (int kbi = 0; kbi < 8; kbi++) {
            uint32_t a[4];
            LDS128(a, abase + (uint32_t)(kbi * 4096 + w * 512 + l * 16));
#pragma unroll
            for (int nb = 0; nb < 32; nb++) {
                uint32_t b0, b1;
                LDS64(b0, b1, bbase + (uint32_t)(kbi * 8192 + nb * 256 + l * 8));
                MMA_TF32(acc[nb], a, b0, b1);
            }
        }
        if (l == 0) MBAR_ARRIVE(sb + LG_CTL + 16 + (s & 1) * 8);
    }

    // bias + log_softmax (rows 16w+g and 16w+g+8; cols spread over quad lanes)
    int g = l >> 2, tig = l & 3;
    float mx0 = -1e30f, mx1 = -1e30f;
#pragma unroll
    for (int nb = 0; nb < 32; nb++) {
        float2 bc = *(const float2*)(g_bcomb + nb * 8 + 2 * tig);
        acc[nb][0] += bc.x; acc[nb][1] += bc.y;
        acc[nb][2] += bc.x; acc[nb][3] += bc.y;
        mx0 = fmaxf(mx0, fmaxf(acc[nb][0], acc[nb][1]));
        mx1 = fmaxf(mx1, fmaxf(acc[nb][2], acc[nb][3]));
    }
    mx0 = fmaxf(mx0, __shfl_xor_sync(0xffffffffu, mx0, 1));
    mx0 = fmaxf(mx0, __shfl_xor_sync(0xffffffffu, mx0, 2));
    mx1 = fmaxf(mx1, __shfl_xor_sync(0xffffffffu, mx1, 1));
    mx1 = fmaxf(mx1, __shfl_xor_sync(0xffffffffu, mx1, 2));
    float s0 = 0.f, s1 = 0.f;
#pragma unroll
    for (int nb = 0; nb < 32; nb++) {
        s0 += __expf(acc[nb][0] - mx0) + __expf(acc[nb][1] - mx0);
        s1 += __expf(acc[nb][2] - mx1) + __expf(acc[nb][3] - mx1);
    }
    s0 += __shfl_xor_sync(0xffffffffu, s0, 1);
    s0 += __shfl_xor_sync(0xffffffffu, s0, 2);
    s1 += __shfl_xor_sync(0xffffffffu, s1, 1);
    s1 += __shfl_xor_sync(0xffffffffu, s1, 2);
    float lse0 = mx0 + logf(s0);
    float lse1 = mx1 + logf(s1);

    int b0r = (w << 4) + g;
    float* d0 = out + ((size_t)b0r * TT + t) * 256 + 2 * tig;
    float* d1 = out + ((size_t)(b0r + 8) * TT + t) * 256 + 2 * tig;
#pragma unroll
    for (int nb = 0; nb < 32; nb++) {
        *(float2*)(d0 + nb * 8) = make_float2(acc[nb][0] - lse0, acc[nb][1] - lse0);
        *(float2*)(d1 + nb * 8) = make_float2(acc[nb][2] - lse1, acc[nb][3] - lse1);
    }
}

// ---------------------------------------------------------------------------------------
extern "C" void kernel_launch(void* const* d_in, const int* in_sizes, int n_in,
                              void* d_out, int out_size) {
    const int*   x        = (const int*)  d_in[0];
    const float* emb      = (const float*)d_in[1];
    const float* lstm_Wih = (const float*)d_in[2];
    const float* lstm_Whh = (const float*)d_in[3];
    const float* lstm_bih = (const float*)d_in[4];
    const float* lstm_bhh = (const float*)d_in[5];
    const float* Wd       = (const float*)d_in[6];
    const float* bd       = (const float*)d_in[7];
    const float* Wo       = (const float*)d_in[8];
    const float* bo       = (const float*)d_in[9];
    const float* s1_Wih   = (const float*)d_in[10];
    const float* s1_bih   = (const float*)d_in[11];
    const float* s1_bhh   = (const float*)d_in[12];
    const float* s1_Wd    = (const float*)d_in[13];
    const float* s1_bd    = (const float*)d_in[14];
    const float* s2_Wih   = (const float*)d_in[15];
    const float* s2_bih   = (const float*)d_in[16];
    const float* s2_bhh   = (const float*)d_in[17];
    const float* s2_Wd    = (const float*)d_in[18];
    const float* s2_bd    = (const float*)d_in[19];
    float* out = (float*)d_out;

    const int rnn_smem = SM_TOTAL + 1024;
    const int lg_smem  = LG_TOTAL + 1024;
    cudaFuncSetAttribute(rnn6_kernel, cudaFuncAttributeMaxDynamicSharedMemorySize, rnn_smem);
    cudaFuncSetAttribute(logits_kernel, cudaFuncAttributeMaxDynamicSharedMemorySize, lg_smem);

    senti_tab_kernel<<<1, 256>>>(emb, s1_Wih, s1_bih, s1_bhh, s1_Wd, s1_bd,
                                 s2_Wih, s2_bih, s2_bhh, s2_Wd, s2_bd);
    tab_kernel<<<VV, 256>>>(emb, lstm_Wih, lstm_bih, lstm_bhh);
    wcomb_kernel<<<VV, 256>>>(Wd, bd, Wo, bo);
    wpack_kernel<<<128, 256>>>();
    init_kernel<<<(HF_T + 255) / 256, 256>>>();

    rnn6_kernel<<<NCTA, 288, rnn_smem>>>(x, lstm_Whh);

    logits_kernel<<<TT, 288, lg_smem>>>(out);
}

// round 13
// speedup vs baseline: 1.5636x; 1.0351x over previous
#include <cuda_runtime.h>
#include <math.h>
#include <stdint.h>

// Problem constants
#define BB   128
#define TT   1024
#define VV   256
#define EE   128
#define HH   1024
#define DD   512
#define SS   5
#define G4H  4096
#define NCTA 128

// h-state in A-fragment layout: [t][kb 0..127][mt 0..7][lane 0..31][slot 0..3] floats
#define HF_T 131072

// rnn smem layout (byte offsets from 1024-aligned base)
#define SM_B   0               // B fragments: 128KB
#define SM_A   131072          // A stages: 2 x 32KB
#define SM_CTL 196608          // full0 +0, full1 +8, free0 +16, free1 +24
#define SM_TOTAL (196608 + 64)

// logits smem layout
#define LG_A   0               // A stages: 2 x 32KB
#define LG_B   65536           // B stages: 2 x 64KB
#define LG_CTL 196608
#define LG_TOTAL (196608 + 64)

// ---------------- device scratch -------------------------------------------------------
__device__ float g_a2tab[VV * SS];
__device__ float g_gx_tab[VV * G4H];
__device__ float g_attn_tab[VV * G4H];
__device__ float g_Wcomb[VV * HH];
__device__ float g_bcomb[VV];
__device__ float g_h0f[HF_T];
__device__ float g_hsf[(size_t)TT * HF_T];
__device__ float2 g_WcombF[128 * 32 * 32];          // Wcomb B-fragments (1 MB)
__device__ int   g_done[TT];                        // per-step completion counters

__device__ __forceinline__ float sigm(float x) { return 1.0f / (1.0f + __expf(-x)); }
__device__ __forceinline__ uint32_t f2tf32(float f) {
    uint32_t u;
    asm("cvt.rna.tf32.f32 %0, %1;" : "=r"(u) : "f"(f));
    return u;
}
__device__ __forceinline__ uint32_t smem_u32(const void* p) {
    uint32_t a;
    asm("{ .reg .u64 t; cvta.to.shared.u64 t, %1; cvt.u32.u64 %0, t; }" : "=r"(a) : "l"(p));
    return a;
}

#define MBAR_INIT(a, n) asm volatile("mbarrier.init.shared.b64 [%0], %1;" :: "r"(a), "r"((uint32_t)(n)) : "memory")
#define MBAR_ARRIVE(a)  asm volatile("mbarrier.arrive.shared.b64 _, [%0];" :: "r"(a) : "memory")
#define MBAR_EXPECT_TX(a, b) asm volatile("mbarrier.arrive.expect_tx.shared.b64 _, [%0], %1;" :: "r"(a), "r"((uint32_t)(b)) : "memory")
#define MBAR_WAIT(a, par) do { \
    uint32_t _m = (a), _p = (par), _d; \
    asm volatile("{ .reg .pred p; mbarrier.try_wait.parity.acquire.cta.shared::cta.b64 p, [%1], %2; selp.b32 %0,1,0,p; }" \
                 : "=r"(_d) : "r"(_m), "r"(_p) : "memory"); \
    if (!_d) { \
        asm volatile("{ .reg .pred P1; WL_%=: mbarrier.try_wait.parity.acquire.cta.shared::cta.b64 P1, [%0], %1, 0x989680; " \
                     "@P1 bra.uni WD_%=; bra.uni WL_%=; WD_%=: }" :: "r"(_m), "r"(_p) : "memory"); \
    } } while (0)

#define BULK_CP(dst, src, bytes, mbar) \
    asm volatile("cp.async.bulk.shared::cluster.global.mbarrier::complete_tx::bytes [%0], [%1], %2, [%3];" \
                 :: "r"(dst), "l"(src), "r"((uint32_t)(bytes)), "r"(mbar) : "memory")

#define LDS128(r, addr) \
    asm volatile("ld.shared.v4.b32 {%0,%1,%2,%3}, [%4];" \
                 : "=r"((r)[0]), "=r"((r)[1]), "=r"((r)[2]), "=r"((r)[3]) : "r"(addr))
#define LDS64(r0, r1, addr) \
    asm volatile("ld.shared.v2.b32 {%0,%1}, [%2];" : "=r"(r0), "=r"(r1) : "r"(addr))

#define MMA_TF32(acc, a, b0, b1) \
    asm volatile("mma.sync.aligned.m16n8k8.row.col.f32.tf32.tf32.f32 " \
                 "{%0,%1,%2,%3}, {%4,%5,%6,%7}, {%8,%9}, {%0,%1,%2,%3};" \
                 : "+f"((acc)[0]), "+f"((acc)[1]), "+f"((acc)[2]), "+f"((acc)[3]) \
                 : "r"((a)[0]), "r"((a)[1]), "r"((a)[2]), "r"((a)[3]), "r"(b0), "r"(b1))

// ---------------- prep kernels ---------------------------------------------------------
__global__ void senti_tab_kernel(const float* __restrict__ emb,
                                 const float* __restrict__ s1_Wih, const float* __restrict__ s1_bih,
                                 const float* __restrict__ s1_bhh, const float* __restrict__ s1_Wd,
                                 const float* __restrict__ s1_bd,
                                 const float* __restrict__ s2_Wih, const float* __restrict__ s2_bih,
                                 const float* __restrict__ s2_bhh, const float* __restrict__ s2_Wd,
                                 const float* __restrict__ s2_bd) {
    int v = blockIdx.x * blockDim.x + threadIdx.x;
    if (v >= VV) return;
    float h1[8];
    {
        float g[32];
        const float* e = emb + v * EE;
        for (int j = 0; j < 32; j++) {
            const float* w = s1_Wih + j * EE;
            float a = s1_bih[j] + s1_bhh[j];
            for (int k = 0; k < EE; k++) a += e[k] * w[k];
            g[j] = a;
        }
        for (int u = 0; u < 8; u++) {
            float cc = sigm(g[u]) * tanhf(g[16 + u]);
            h1[u] = sigm(g[24 + u]) * tanhf(cc);
        }
    }
    float a1[SS];
    {
        float l[SS], m = -1e30f;
        for (int s = 0; s < SS; s++) {
            float a = s1_bd[s];
            for (int u = 0; u < 8; u++) a += h1[u] * s1_Wd[s * 8 + u];
            l[s] = a; m = fmaxf(m, a);
        }
        float sum = 0.0f;
        for (int s = 0; s < SS; s++) { l[s] = __expf(l[s] - m); sum += l[s]; }
        for (int s = 0; s < SS; s++) a1[s] = l[s] / sum;
    }
    float h2[8];
    {
        float g[32];
        for (int j = 0; j < 32; j++) {
            const float* w = s2_Wih + j * SS;
            float a = s2_bih[j] + s2_bhh[j];
            for (int s = 0; s < SS; s++) a += a1[s] * w[s];
            g[j] = a;
        }
        for (int u = 0; u < 8; u++) {
            float cc = sigm(g[u]) * tanhf(g[16 + u]);
            h2[u] = sigm(g[24 + u]) * tanhf(cc);
        }
    }
    {
        float l[SS], m = -1e30f;
        for (int s = 0; s < SS; s++) {
            float a = s2_bd[s];
            for (int u = 0; u < 8; u++) a += h2[u] * s2_Wd[s * 8 + u];
            l[s] = a; m = fmaxf(m, a);
        }
        float sum = 0.0f;
        for (int s = 0; s < SS; s++) { l[s] = __expf(l[s] - m); sum += l[s]; }
        for (int s = 0; s < SS; s++) g_a2tab[v * SS + s] = l[s] / sum;
    }
}

__global__ __launch_bounds__(256) void tab_kernel(const float* __restrict__ emb,
                                                  const float* __restrict__ Wih,
                                                  const float* __restrict__ bih,
                                                  const float* __restrict__ bhh) {
    int v = blockIdx.x;
    __shared__ float se[EE];
    __shared__ float sa[SS];
    if (threadIdx.x < EE) se[threadIdx.x] = emb[v * EE + threadIdx.x];
    if (threadIdx.x < SS) sa[threadIdx.x] = g_a2tab[v * SS + threadIdx.x];
    __syncthreads();
    for (int j = threadIdx.x; j < G4H; j += 256) {
        const float* w = Wih + (size_t)j * (EE + SS);
        float a = bih[j] + bhh[j];
        for (int k = 0; k < EE; k++) a += se[k] * w[k];
        g_gx_tab[v * G4H + j] = a;
        float at = 0.0f;
        for (int s = 0; s < SS; s++) at += sa[s] * w[EE + s];
        g_attn_tab[v * G4H + j] = at;
    }
}

__global__ __launch_bounds__(256) void wcomb_kernel(const float* __restrict__ Wd,
                                                    const float* __restrict__ bd,
                                                    const float* __restrict__ Wo,
                                                    const float* __restrict__ bo) {
    int o = blockIdx.x;
    __shared__ float swo[DD];
    for (int i = threadIdx.x; i < DD; i += 256) swo[i] = Wo[o * DD + i];
    __syncthreads();
    for (int k = threadIdx.x; k < HH; k += 256) {
        float a = 0.0f;
        for (int d = 0; d < DD; d++) a += swo[d] * Wd[d * HH + k];
        g_Wcomb[o * HH + k] = a;
    }
    if (threadIdx.x == 0) {
        float a = bo[o];
        for (int d = 0; d < DD; d++) a += swo[d] * bd[d];
        g_bcomb[o] = a;
    }
}

// pack Wcomb into B-fragment layout (tf32-rounded): [kb][nblk][lane] float2
__global__ __launch_bounds__(256) void wpack_kernel() {
    int kb = blockIdx.x;
    for (int i = threadIdx.x; i < 1024; i += 256) {
        int nb = i >> 5, L = i & 31;
        int o = nb * 8 + (L >> 2);
        int k = kb * 8 + (L & 3);
        float2 v;
        v.x = __uint_as_float(f2tf32(g_Wcomb[(size_t)o * HH + k]));
        v.y = __uint_as_float(f2tf32(g_Wcomb[(size_t)o * HH + k + 4]));
        g_WcombF[(kb * 32 + nb) * 32 + L] = v;
    }
}

__global__ void init_kernel() {
    int idx = blockIdx.x * blockDim.x + threadIdx.x;
    if (idx < HF_T) g_h0f[idx] = 0.0f;
    if (idx < TT) g_done[idx] = 0;
}

// ---------------- persistent recurrence: fused MMA+pointwise, dataflow producer --------
// 128 CTAs x 288 thr. CTA jt owns cols c = gate*8+uu (Whh row j = gate*1024 + jt*8 + uu).
// Warps 0-7: MMA consumers (m16 rows each: rows 16w..16w+15) with FUSED LSTM pointwise
//            (C fragment holds all 4 gates for this thread's (b,u) pairs; cell state in
//            registers; h stored directly in A-fragment layout).
// Warp 8 lane 0: producer; per step polls g_done[t-1]==128 once, then 16 bulk copies.
__global__ __launch_bounds__(288, 1) void rnn7_kernel(const int* __restrict__ x,
                                                      const float* __restrict__ Whh) {
    extern __shared__ char smraw[];
    uint32_t sb0 = smem_u32(smraw);
    uint32_t sb = (sb0 + 1023u) & ~1023u;
    char* smem = smraw + (sb - sb0);

    const int tid = threadIdx.x;
    const int jt  = blockIdx.x;
    const int w   = tid >> 5;
    const int l   = tid & 31;

    // ---- pack B fragments (tf32-rounded): [kb][np][lane] 16B ----
    {
        float4* Bp = (float4*)(smem + SM_B);
        for (int i = tid; i < 8192; i += 288) {
            int kb = i >> 6;
            int np = (i >> 5) & 1;
            int L  = i & 31;
            int tig = L & 3, g0 = L >> 2;
            int j0 = (2 * np) * 1024 + jt * 8 + g0;
            int j1 = j0 + 1024;
            int k0 = kb * 8 + tig;
            float4 v;
            v.x = __uint_as_float(f2tf32(Whh[(size_t)j0 * HH + k0]));
            v.y = __uint_as_float(f2tf32(Whh[(size_t)j0 * HH + k0 + 4]));
            v.z = __uint_as_float(f2tf32(Whh[(size_t)j1 * HH + k0]));
            v.w = __uint_as_float(f2tf32(Whh[(size_t)j1 * HH + k0 + 4]));
            Bp[i] = v;
        }
    }
    if (tid == 0) {
        MBAR_INIT(sb + SM_CTL + 0, 1);    // full buf0
        MBAR_INIT(sb + SM_CTL + 8, 1);    // full buf1
        MBAR_INIT(sb + SM_CTL + 16, 8);   // free buf0 (8 consumer warps)
        MBAR_INIT(sb + SM_CTL + 24, 8);   // free buf1
    }
    __syncthreads();

    // =========================== producer warp ===========================
    if (w == 8) {
        if (l != 0) return;
        for (int t = 0; t < TT; t++) {
            const float* src;
            if (t == 0) {
                src = g_h0f;
            } else {
                src = g_hsf + (size_t)(t - 1) * HF_T;
                int v;
                do {
                    asm volatile("ld.global.cg.b32 %0, [%1];" : "=r"(v) : "l"(g_done + (t - 1)) : "memory");
                    if (v >= NCTA) break;
                    __nanosleep(32);
                } while (1);
                __threadfence();
            }
            for (int s = 0; s < 16; s++) {
                unsigned u = (unsigned)(t * 8 + (s >> 1));
                if (u > 0) MBAR_WAIT(sb + SM_CTL + 16 + (s & 1) * 8, (u - 1) & 1u);
                MBAR_EXPECT_TX(sb + SM_CTL + (s & 1) * 8, 32768);
                BULK_CP(sb + SM_A + (s & 1) * 32768, src + s * 8192, 32768,
                        sb + SM_CTL + (s & 1) * 8);
            }
        }
        return;
    }

    // ================== fused consumer + pointwise warps (0-7) ==================
    {
        const int g   = l >> 2;
        const int tig = l & 3;
        const int b0r = (w << 4) + g;        // row in m16 tile (ri = g < 8)
        const int b1r = b0r + 8;             // (ri = g+8 >= 8)
        const int u0  = 2 * tig;             // this thread's unit columns
        const int sbase = (u0 >= 4) ? 2 : 0; // slot base (u0,u0+1 on same side of 4)
        float creg[4] = {0.f, 0.f, 0.f, 0.f};   // cell: (b0,u0),(b0,u1),(b1,u0),(b1,u1)

        for (int t = 0; t < TT; t++) {
            // ---- prefetch gate-input table rows (tokens known at step start) ----
            float ga[4][4];   // [gate][q]: q0=(b0,u0) q1=(b0,u1) q2=(b1,u0) q3=(b1,u1)
            {
                int tok0 = __ldg(&x[b0r * TT + t]);
                int tok1 = __ldg(&x[b1r * TT + t]);
                const float* gx0 = g_gx_tab + (size_t)tok0 * G4H + (jt << 3) + u0;
                const float* gx1 = g_gx_tab + (size_t)tok1 * G4H + (jt << 3) + u0;
#pragma unroll
                for (int nb = 0; nb < 4; nb++) {
                    float2 p0 = *(const float2*)(gx0 + (nb << 10));
                    float2 p1 = *(const float2*)(gx1 + (nb << 10));
                    ga[nb][0] = p0.x; ga[nb][1] = p0.y;
                    ga[nb][2] = p1.x; ga[nb][3] = p1.y;
                }
                if (t > 0) {
                    int pt0 = __ldg(&x[b0r * TT + t - 1]);
                    int pt1 = __ldg(&x[b1r * TT + t - 1]);
                    const float* at0 = g_attn_tab + (size_t)pt0 * G4H + (jt << 3) + u0;
                    const float* at1 = g_attn_tab + (size_t)pt1 * G4H + (jt << 3) + u0;
#pragma unroll
                    for (int nb = 0; nb < 4; nb++) {
                        float2 p0 = *(const float2*)(at0 + (nb << 10));
                        float2 p1 = *(const float2*)(at1 + (nb << 10));
                        ga[nb][0] += p0.x; ga[nb][1] += p0.y;
                        ga[nb][2] += p1.x; ga[nb][3] += p1.y;
                    }
                }
            }

            // ---- MMA over 16 stages ----
            float acc[4][4];
#pragma unroll
            for (int nb = 0; nb < 4; nb++)
#pragma unroll
                for (int q = 0; q < 4; q++) acc[nb][q] = 0.f;

            for (int s = 0; s < 16; s++) {
                unsigned u = (unsigned)(t * 8 + (s >> 1));
                MBAR_WAIT(sb + SM_CTL + (s & 1) * 8, u & 1u);
                uint32_t abase = sb + SM_A + (s & 1) * 32768;
#pragma unroll
                for (int kbi = 0; kbi < 8; kbi++) {
                    int kb = s * 8 + kbi;
                    uint32_t aaddr = abase + (uint32_t)(((kbi * 8 + w) * 32 + l) * 16);
                    uint32_t baddr = sb + SM_B + (uint32_t)(((kb * 2) * 32 + l) * 16);
                    uint32_t a[4], b0[4], b1[4];
                    LDS128(a, aaddr);
                    LDS128(b0, baddr);
                    LDS128(b1, baddr + 512);
                    MMA_TF32(acc[0], a, b0[0], b0[1]);
                    MMA_TF32(acc[1], a, b0[2], b0[3]);
                    MMA_TF32(acc[2], a, b1[0], b1[1]);
                    MMA_TF32(acc[3], a, b1[2], b1[3]);
                }
                if (l == 0) MBAR_ARRIVE(sb + SM_CTL + 16 + (s & 1) * 8);
            }

            // ---- fused LSTM pointwise in registers ----
            float* hdst = g_hsf + ((size_t)t * 128 + jt) * 1024 + (w << 7);
            float hv[4];
#pragma unroll
            for (int q = 0; q < 4; q++) {
                float gi = acc[0][q] + ga[0][q];
                float gf = acc[1][q] + ga[1][q];
                float gg = acc[2][q] + ga[2][q];
                float go = acc[3][q] + ga[3][q];
                float cn = sigm(gf) * creg[q] + sigm(gi) * tanhf(gg);
                float hn = sigm(go) * tanhf(cn);
                creg[q] = cn;
                hv[q] = __uint_as_float(f2tf32(hn));
            }
            // stores: L = g*4 + (uu&3); slot = sbase + (row>=8 ? 1 : 0)
            int L0 = (g << 2) + (u0 & 3);
            int L1 = (g << 2) + ((u0 + 1) & 3);
            hdst[(L0 << 2) + sbase]     = hv[0];
            hdst[(L1 << 2) + sbase]     = hv[1];
            hdst[(L0 << 2) + sbase + 1] = hv[2];
            hdst[(L1 << 2) + sbase + 1] = hv[3];

            __threadfence();
            asm volatile("bar.sync 1, 256;" ::: "memory");   // all 8 warps' stores fenced
            if (tid == 0) atomicAdd(&g_done[t], 1);
        }
    }
}

// ---------------- epilogue: tf32 MMA logits + log_softmax ------------------------------
// 1024 CTAs (one per t) x 288 thr. Warps 0-7: m16 rows each, all 256 cols.
// Warp 8 lane 0: bulk-copy producer (A chunk 32KB + B chunk 64KB per stage).
__global__ __launch_bounds__(288, 1) void logits_kernel(float* __restrict__ out) {
    extern __shared__ char smraw[];
    uint32_t sb0 = smem_u32(smraw);
    uint32_t sb = (sb0 + 1023u) & ~1023u;

    const int t = blockIdx.x;
    const int tid = threadIdx.x;
    const int w = tid >> 5;
    const int l = tid & 31;

    if (tid == 0) {
        MBAR_INIT(sb + LG_CTL + 0, 1);
        MBAR_INIT(sb + LG_CTL + 8, 1);
        MBAR_INIT(sb + LG_CTL + 16, 8);
        MBAR_INIT(sb + LG_CTL + 24, 8);
    }
    __syncthreads();

    if (w == 8) {
        if (l == 0) {
            const char* asrc = (const char*)(g_hsf + (size_t)t * HF_T);
            const char* bsrc = (const char*)g_WcombF;
            for (int s = 0; s < 16; s++) {
                int k = s >> 1;
                if (s >= 2) MBAR_WAIT(sb + LG_CTL + 16 + (s & 1) * 8, (unsigned)((k - 1) & 1));
                MBAR_EXPECT_TX(sb + LG_CTL + (s & 1) * 8, 98304);
                BULK_CP(sb + LG_A + (s & 1) * 32768, asrc + s * 32768, 32768,
                        sb + LG_CTL + (s & 1) * 8);
                BULK_CP(sb + LG_B + (s & 1) * 65536, bsrc + s * 65536, 65536,
                        sb + LG_CTL + (s & 1) * 8);
            }
        }
        return;
    }

    float acc[32][4];
#pragma unroll
    for (int nb = 0; nb < 32; nb++)
#pragma unroll
        for (int q = 0; q < 4; q++) acc[nb][q] = 0.f;

    for (int s = 0; s < 16; s++) {
        MBAR_WAIT(sb + LG_CTL + (s & 1) * 8, (unsigned)((s >> 1) & 1));
        uint32_t abase = sb + LG_A + (s & 1) * 32768;
        uint32_t bbase = sb + LG_B + (s & 1) * 65536;
#pragma unroll 2
        for (int kbi = 0; kbi < 8; kbi++) {
            uint32_t a[4];
            LDS128(a, abase + (uint32_t)(kbi * 4096 + w * 512 + l * 16));
#pragma unroll
            for (int nb = 0; nb < 32; nb++) {
                uint32_t b0, b1;
                LDS64(b0, b1, bbase + (uint32_t)(kbi * 8192 + nb * 256 + l * 8));
                MMA_TF32(acc[nb], a, b0, b1);
            }
        }
        if (l == 0) MBAR_ARRIVE(sb + LG_CTL + 16 + (s & 1) * 8);
    }

    // bias + log_softmax (rows 16w+g and 16w+g+8; cols spread over quad lanes)
    int g = l >> 2, tig = l & 3;
    float mx0 = -1e30f, mx1 = -1e30f;
#pragma unroll
    for (int nb = 0; nb < 32; nb++) {
        float2 bc = *(const float2*)(g_bcomb + nb * 8 + 2 * tig);
        acc[nb][0] += bc.x; acc[nb][1] += bc.y;
        acc[nb][2] += bc.x; acc[nb][3] += bc.y;
        mx0 = fmaxf(mx0, fmaxf(acc[nb][0], acc[nb][1]));
        mx1 = fmaxf(mx1, fmaxf(acc[nb][2], acc[nb][3]));
    }
    mx0 = fmaxf(mx0, __shfl_xor_sync(0xffffffffu, mx0, 1));
    mx0 = fmaxf(mx0, __shfl_xor_sync(0xffffffffu, mx0, 2));
    mx1 = fmaxf(mx1, __shfl_xor_sync(0xffffffffu, mx1, 1));
    mx1 = fmaxf(mx1, __shfl_xor_sync(0xffffffffu, mx1, 2));
    float s0 = 0.f, s1 = 0.f;
#pragma unroll
    for (int nb = 0; nb < 32; nb++) {
        s0 += __expf(acc[nb][0] - mx0) + __expf(acc[nb][1] - mx0);
        s1 += __expf(acc[nb][2] - mx1) + __expf(acc[nb][3] - mx1);
    }
    s0 += __shfl_xor_sync(0xffffffffu, s0, 1);
    s0 += __shfl_xor_sync(0xffffffffu, s0, 2);
    s1 += __shfl_xor_sync(0xffffffffu, s1, 1);
    s1 += __shfl_xor_sync(0xffffffffu, s1, 2);
    float lse0 = mx0 + logf(s0);
    float lse1 = mx1 + logf(s1);

    int b0r = (w << 4) + g;
    float* d0 = out + ((size_t)b0r * TT + t) * 256 + 2 * tig;
    float* d1 = out + ((size_t)(b0r + 8) * TT + t) * 256 + 2 * tig;
#pragma unroll
    for (int nb = 0; nb < 32; nb++) {
        *(float2*)(d0 + nb * 8) = make_float2(acc[nb][0] - lse0, acc[nb][1] - lse0);
        *(float2*)(d1 + nb * 8) = make_float2(acc[nb][2] - lse1, acc[nb][3] - lse1);
    }
}

// ---------------------------------------------------------------------------------------
extern "C" void kernel_launch(void* const* d_in, const int* in_sizes, int n_in,
                              void* d_out, int out_size) {
    const int*   x        = (const int*)  d_in[0];
    const float* emb      = (const float*)d_in[1];
    const float* lstm_Wih = (const float*)d_in[2];
    const float* lstm_Whh = (const float*)d_in[3];
    const float* lstm_bih = (const float*)d_in[4];
    const float* lstm_bhh = (const float*)d_in[5];
    const float* Wd       = (const float*)d_in[6];
    const float* bd       = (const float*)d_in[7];
    const float* Wo       = (const float*)d_in[8];
    const float* bo       = (const float*)d_in[9];
    const float* s1_Wih   = (const float*)d_in[10];
    const float* s1_bih   = (const float*)d_in[11];
    const float* s1_bhh   = (const float*)d_in[12];
    const float* s1_Wd    = (const float*)d_in[13];
    const float* s1_bd    = (const float*)d_in[14];
    const float* s2_Wih   = (const float*)d_in[15];
    const float* s2_bih   = (const float*)d_in[16];
    const float* s2_bhh   = (const float*)d_in[17];
    const float* s2_Wd    = (const float*)d_in[18];
    const float* s2_bd    = (const float*)d_in[19];
    float* out = (float*)d_out;

    const int rnn_smem = SM_TOTAL + 1024;
    const int lg_smem  = LG_TOTAL + 1024;
    cudaFuncSetAttribute(rnn7_kernel, cudaFuncAttributeMaxDynamicSharedMemorySize, rnn_smem);
    cudaFuncSetAttribute(logits_kernel, cudaFuncAttributeMaxDynamicSharedMemorySize, lg_smem);

    // order chosen so the recurrence kernel lands in ncu's capture slot
    init_kernel<<<(HF_T + 255) / 256, 256>>>();
    senti_tab_kernel<<<1, 256>>>(emb, s1_Wih, s1_bih, s1_bhh, s1_Wd, s1_bd,
                                 s2_Wih, s2_bih, s2_bhh, s2_Wd, s2_bd);
    tab_kernel<<<VV, 256>>>(emb, lstm_Wih, lstm_bih, lstm_bhh);

    rnn7_kernel<<<NCTA, 288, rnn_smem>>>(x, lstm_Whh);

    wcomb_kernel<<<VV, 256>>>(Wd, bd, Wo, bo);
    wpack_kernel<<<128, 256>>>();
    logits_kernel<<<TT, 288, lg_smem>>>(out);
}